// round 14
// baseline (speedup 1.0000x reference)
#include <cuda_runtime.h>
#include <cuda_bf16.h>
#include <cstdint>

#define N_NODES 50000
#define N_EDGES 400000
#define IN_C 32
#define OUT_C 32
#define EDGE_DIM 16
#define HIDDEN 128
#define BN_EPS 1e-5f

#define A_COLS (HIDDEN * IN_C)   // 4096
#define A_U32 (A_COLS / 2)       // 2048 packed u32 per node per plane
#define BN_BLOCKS 232

// tcgen05 GEMM tiling
#define TCM 128
#define KT2 64
#define NK2 (A_COLS / KT2)        // 64
#define TCGRID ((N_NODES + TCM - 1) / TCM)   // 391
#define BUFSZ 40960
#define TC_DYN (2 * BUFSZ + 1024)
#define TC_IDESC 0x8080490u       // c=F32, a/b=BF16 K-major, M=128, N=32

// fallback (R11-exact) tiling
#define FBM 128
#define FBK 32
#define FNKT (A_COLS / FBK)       // 128
#define FASTR 40
#define FWSTR 40

// abuild: node-group blocking
#define GNODES 16
#define ECAP 128
#define NGROUPS ((N_NODES + GNODES - 1) / GNODES)   // 3125

// tcgen05 availability: only in arch-specific ('a') device passes
#if defined(__CUDA_ARCH__) && (defined(__CUDA_ARCH_FEAT_SM103_ALL) || \
    defined(__CUDA_ARCH_FEAT_SM100_ALL) || defined(__CUDA_ARCH_FEAT_SM101_ALL) || \
    defined(__CUDA_ARCH_SPECIFIC__))
#define HAS_TC 1
#else
#define HAS_TC 0
#endif

// ---------------- static device scratch (no allocations allowed) ------------
__device__ uint32_t g_Ah[(size_t)N_NODES * A_U32];
__device__ uint32_t g_Al[(size_t)N_NODES * A_U32];
__device__ uint32_t g_w2h[128 * 512];
__device__ uint32_t g_w2l[128 * 512];
__device__ float g_xsum[(size_t)N_NODES * IN_C];
__device__ float g_h[(size_t)N_NODES * OUT_C];
__device__ int   g_hist[N_NODES];   // zero at load; re-zeroed by scan each run
__device__ int   g_off[N_NODES + 1];
__device__ int   g_cursor[N_NODES];
__device__ int   g_perm[N_EDGES];
__device__ int   g_flag;            // scan->scatter release; reset by k_hist
__device__ double g_psum[BN_BLOCKS][OUT_C];
__device__ double g_psq[BN_BLOCKS][OUT_C];
__device__ float g_scale[OUT_C];
__device__ float g_shift[OUT_C];

// ---------------- helpers ----------------------------------------------------
__device__ __forceinline__ void split_bf(float v, __nv_bfloat16& h,
                                         __nv_bfloat16& l) {
    h = __float2bfloat16_rn(v);
    l = __float2bfloat16_rn(v - __bfloat162float(h));
}

__device__ __forceinline__ uint32_t pack_bf(__nv_bfloat16 a, __nv_bfloat16 b) {
    __nv_bfloat162 p;
    p.x = a; p.y = b;
    return *reinterpret_cast<uint32_t*>(&p);
}

__device__ __forceinline__ uint32_t lds_u32(const __nv_bfloat16* p) {
    return *reinterpret_cast<const uint32_t*>(p);
}

__device__ __forceinline__ void mma16816(float c[4], uint32_t a0, uint32_t a1,
                                         uint32_t a2, uint32_t a3, uint32_t b0,
                                         uint32_t b1) {
    asm volatile(
        "mma.sync.aligned.m16n8k16.row.col.f32.bf16.bf16.f32 "
        "{%0,%1,%2,%3}, {%4,%5,%6,%7}, {%8,%9}, {%0,%1,%2,%3};"
        : "+f"(c[0]), "+f"(c[1]), "+f"(c[2]), "+f"(c[3])
        : "r"(a0), "r"(a1), "r"(a2), "r"(a3), "r"(b0), "r"(b1));
}

// packed f32x2 ops (sm_100+)
__device__ __forceinline__ unsigned long long pack2(float a, float b) {
    unsigned long long r;
    asm("mov.b64 %0, {%1, %2};" : "=l"(r) : "f"(a), "f"(b));
    return r;
}
__device__ __forceinline__ void unpack2(unsigned long long v, float& a, float& b) {
    asm("mov.b64 {%0, %1}, %2;" : "=f"(a), "=f"(b) : "l"(v));
}
__device__ __forceinline__ void fma2(unsigned long long& d, unsigned long long a,
                                     unsigned long long b) {
    asm("fma.rn.f32x2 %0, %1, %2, %0;" : "+l"(d) : "l"(a), "l"(b));
}
__device__ __forceinline__ unsigned long long mul2(unsigned long long a,
                                                   unsigned long long b) {
    unsigned long long r;
    asm("mul.rn.f32x2 %0, %1, %2;" : "=l"(r) : "l"(a), "l"(b));
    return r;
}

// self-detecting edge-index load (int32 vs int64 buffer layout)
__device__ __forceinline__ int detect64(const void* ei) {
    const int* p = (const int*)ei;
    return (p[1] == 0) & (p[3] == 0) & (p[5] == 0) & (p[7] == 0);
}
__device__ __forceinline__ int load_idx(const void* ei, int is64, long long elem) {
    int v = is64 ? (int)((const long long*)ei)[elem] : ((const int*)ei)[elem];
    return min(max(v, 0), N_NODES - 1);
}

// ---------------- smem primitives --------------------------------------------
__device__ __forceinline__ uint32_t smem_u32(const void* p) {
    uint32_t a;
    asm("{ .reg .u64 t; cvta.to.shared.u64 t, %1; cvt.u32.u64 %0, t; }"
        : "=r"(a) : "l"(p));
    return a;
}
__device__ __forceinline__ uint32_t swz128(uint32_t off) {
    return off ^ ((off >> 3) & 0x70);
}

#if HAS_TC
__device__ __forceinline__ uint32_t elect_one() {
    uint32_t pred;
    asm volatile("{\n\t.reg .pred p;\n\telect.sync _|p, 0xFFFFFFFF;\n\t"
                 "selp.b32 %0, 1, 0, p;\n\t}" : "=r"(pred));
    return pred;
}
__device__ __forceinline__ void mbar_init(uint32_t a, uint32_t c) {
    asm volatile("mbarrier.init.shared.b64 [%0], %1;" :: "r"(a), "r"(c) : "memory");
}
__device__ __forceinline__ void mbar_wait(uint32_t a, uint32_t par) {
    asm volatile(
        "{\n\t.reg .pred P;\n\t"
        "WL%=:\n\t"
        "mbarrier.try_wait.parity.acquire.cta.shared::cta.b64 P, [%0], %1;\n\t"
        "@!P bra WL%=;\n\t}"
        :: "r"(a), "r"(par) : "memory");
}
__device__ __forceinline__ void tc_alloc(uint32_t slot, uint32_t ncols) {
    asm volatile("tcgen05.alloc.cta_group::1.sync.aligned.shared::cta.b32 [%0], %1;"
                 :: "r"(slot), "r"(ncols) : "memory");
}
__device__ __forceinline__ void tc_relinq() {
    asm volatile("tcgen05.relinquish_alloc_permit.cta_group::1.sync.aligned;");
}
__device__ __forceinline__ void tc_dealloc(uint32_t base, uint32_t ncols) {
    asm volatile("tcgen05.dealloc.cta_group::1.sync.aligned.b32 %0, %1;"
                 :: "r"(base), "r"(ncols));
}
__device__ __forceinline__ void tc_commit(uint32_t mbar) {
    asm volatile(
        "tcgen05.commit.cta_group::1.mbarrier::arrive::one.shared::cluster.b64 [%0];"
        :: "r"(mbar) : "memory");
}
__device__ __forceinline__ void tc_fence_after() {
    asm volatile("tcgen05.fence::after_thread_sync;" ::: "memory");
}
__device__ __forceinline__ void fence_async_shared() {
    asm volatile("fence.proxy.async.shared::cta;" ::: "memory");
}
__device__ __forceinline__ void tc_mma_f16_ss(uint32_t d, uint64_t a, uint64_t b,
                                              uint32_t idesc, bool acc) {
    uint32_t en = acc ? 1u : 0u;
    asm volatile(
        "{\n\t.reg .pred p;\n\tsetp.ne.u32 p, %5, 0;\n\t"
        "tcgen05.mma.cta_group::1.kind::f16 [%0], %1, %2, %3, {%4, %4, %4, %4}, p;\n\t}"
        :: "r"(d), "l"(a), "l"(b), "r"(idesc), "r"(0u), "r"(en) : "memory");
}
__device__ __forceinline__ void tc_ld32(uint32_t* r, uint32_t addr) {
    asm volatile(
        "tcgen05.ld.sync.aligned.32x32b.x32.b32 "
        "{%0,%1,%2,%3,%4,%5,%6,%7,%8,%9,%10,%11,%12,%13,%14,%15,"
        "%16,%17,%18,%19,%20,%21,%22,%23,%24,%25,%26,%27,%28,%29,%30,%31}, [%32];"
        : "=r"(r[0]), "=r"(r[1]), "=r"(r[2]), "=r"(r[3]), "=r"(r[4]), "=r"(r[5]),
          "=r"(r[6]), "=r"(r[7]), "=r"(r[8]), "=r"(r[9]), "=r"(r[10]), "=r"(r[11]),
          "=r"(r[12]), "=r"(r[13]), "=r"(r[14]), "=r"(r[15]), "=r"(r[16]),
          "=r"(r[17]), "=r"(r[18]), "=r"(r[19]), "=r"(r[20]), "=r"(r[21]),
          "=r"(r[22]), "=r"(r[23]), "=r"(r[24]), "=r"(r[25]), "=r"(r[26]),
          "=r"(r[27]), "=r"(r[28]), "=r"(r[29]), "=r"(r[30]), "=r"(r[31])
        : "r"(addr));
}
__device__ __forceinline__ void tc_wait_ld() {
    asm volatile("tcgen05.wait::ld.sync.aligned;" ::: "memory");
}
__device__ __forceinline__ uint64_t mk_desc(uint32_t base) {
    return ((uint64_t)2 << 61) | ((uint64_t)1 << 46) | ((uint64_t)64 << 32) |
           ((uint64_t)1 << 16) | ((uint64_t)(base >> 4) & 0x3FFF);
}
#endif  // HAS_TC

// ---------------- launch 1: histogram + W2 pre-split + flag reset ------------
__global__ void k_hist(const void* __restrict__ ei, const float* __restrict__ w2) {
    if (blockIdx.x == 0 && threadIdx.x == 0) g_flag = 0;
    int is64 = detect64(ei);
    for (int i = blockIdx.x * blockDim.x + threadIdx.x; i < N_EDGES;
         i += gridDim.x * blockDim.x) {
        int dst = load_idx(ei, is64, (long long)N_EDGES + i);
        atomicAdd(&g_hist[dst], 1);
    }
    for (int id = blockIdx.x * blockDim.x + threadIdx.x; id < 128 * 512;
         id += gridDim.x * blockDim.x) {
        int kt = id >> 9, r = id & 511;
        int n = r >> 4, kp = r & 15;
        int k0 = kt * 32 + 2 * kp;
        float v0 = w2[(size_t)k0 * 32 + n];
        float v1 = w2[(size_t)(k0 + 1) * 32 + n];
        __nv_bfloat16 h0, l0, h1, l1;
        split_bf(v0, h0, l0);
        split_bf(v1, h1, l1);
        g_w2h[id] = pack_bf(h0, h1);
        g_w2l[id] = pack_bf(l0, l1);
    }
}

// ---------------- launch 2: fused scan (block 0) + scatter (all blocks) -----
__device__ __forceinline__ int block_excl_scan1024(int v, int* ws) {
    int tid = threadIdx.x;
    int lane = tid & 31, wid = tid >> 5;
    int incl = v;
#pragma unroll
    for (int o = 1; o < 32; o <<= 1) {
        int nv = __shfl_up_sync(0xffffffffu, incl, o);
        if (lane >= o) incl += nv;
    }
    if (lane == 31) ws[wid] = incl;
    __syncthreads();
    if (wid == 0) {
        int wv = ws[lane];
#pragma unroll
        for (int o = 1; o < 32; o <<= 1) {
            int nv = __shfl_up_sync(0xffffffffu, wv, o);
            if (lane >= o) wv += nv;
        }
        ws[lane] = wv;
    }
    __syncthreads();
    int base = (wid > 0) ? ws[wid - 1] : 0;
    return base + incl - v;
}

__global__ void __launch_bounds__(1024) k_scan_scatter(const void* __restrict__ ei) {
    __shared__ int ws[32];
    __shared__ int s_carry;
    int tid = threadIdx.x;

    if (blockIdx.x == 0) {
        // ---- single-block scan over g_hist; also re-zeros g_hist ----
        if (tid == 0) s_carry = 0;
        __syncthreads();
        for (int base = 0; base < N_NODES; base += 1024) {
            int idx = base + tid;
            int v = (idx < N_NODES) ? g_hist[idx] : 0;
            int ex = block_excl_scan1024(v, ws);
            int c = s_carry;
            if (idx < N_NODES) {
                g_off[idx] = c + ex;
                g_cursor[idx] = c + ex;
                g_hist[idx] = 0;
            }
            __syncthreads();
            if (tid == 1023) s_carry = c + ex + v;
            __syncthreads();
        }
        if (tid == 0) {
            g_off[N_NODES] = N_EDGES;
            __threadfence();
            *(volatile int*)&g_flag = 1;   // release
        }
        __syncthreads();
    } else {
        if (tid == 0) {
            while (*(volatile int*)&g_flag == 0) __nanosleep(200);
        }
        __syncthreads();
        __threadfence();                   // acquire
    }

    // ---- scatter (all blocks, incl. block 0 after its scan) ----
    int is64 = detect64(ei);
    for (int i = blockIdx.x * 1024 + tid; i < N_EDGES; i += gridDim.x * 1024) {
        int dst = load_idx(ei, is64, (long long)N_EDGES + i);
        int pos = atomicAdd(&g_cursor[dst], 1);
        g_perm[pos] = i;
    }
}

// ---------------- launch 3: A build (R11 exact) ------------------------------
__device__ __forceinline__ void stage_edges(int estart, int cnt, int tid,
                                            int is64, const void* ei,
                                            const float* ea, const float* x,
                                            int* s_e, int* s_src,
                                            float4 (*s_ea)[4],
                                            float4 (*s_xj)[8]) {
    __syncthreads();
    for (int j = tid; j < cnt; j += 128) {
        int e = g_perm[estart + j];
        s_e[j] = e;
        s_src[j] = load_idx(ei, is64, e);
    }
    __syncthreads();
    for (int idx = tid; idx < cnt * 4; idx += 128) {
        int j = idx >> 2, q = idx & 3;
        s_ea[j][q] = ((const float4*)(ea + (size_t)s_e[j] * EDGE_DIM))[q];
    }
    for (int idx = tid; idx < cnt * 8; idx += 128) {
        int j = idx >> 3, q = idx & 7;
        s_xj[j][q] = ((const float4*)(x + (size_t)s_src[j] * IN_C))[q];
    }
    __syncthreads();
}

__device__ __forceinline__ void accum_edge(int j, int tid,
                                           const unsigned long long* w1r2,
                                           float b1v,
                                           unsigned long long* acc2, float& xs,
                                           float4 (*s_ea)[4],
                                           float4 (*s_xj)[8]) {
    float4 e0 = s_ea[j][0], e1 = s_ea[j][1], e2 = s_ea[j][2], e3 = s_ea[j][3];
    unsigned long long h2a = mul2(pack2(e0.x, e0.y), w1r2[0]);
    unsigned long long h2b = mul2(pack2(e0.z, e0.w), w1r2[1]);
    fma2(h2a, pack2(e1.x, e1.y), w1r2[2]);
    fma2(h2b, pack2(e1.z, e1.w), w1r2[3]);
    fma2(h2a, pack2(e2.x, e2.y), w1r2[4]);
    fma2(h2b, pack2(e2.z, e2.w), w1r2[5]);
    fma2(h2a, pack2(e3.x, e3.y), w1r2[6]);
    fma2(h2b, pack2(e3.z, e3.w), w1r2[7]);
    float alo, ahi, blo, bhi;
    unpack2(h2a, alo, ahi);
    unpack2(h2b, blo, bhi);
    float he = fmaxf((alo + blo) + (ahi + bhi) + b1v, 0.f);
    unsigned long long he2 = pack2(he, he);
#pragma unroll
    for (int q = 0; q < 8; q++) {
        float4 xv = s_xj[j][q];
        fma2(acc2[2 * q], he2, pack2(xv.x, xv.y));
        fma2(acc2[2 * q + 1], he2, pack2(xv.z, xv.w));
    }
    if (tid < IN_C) xs += ((const float*)s_xj)[j * 32 + tid];
}

__device__ __forceinline__ void store_node(int n, int tid,
                                           const unsigned long long* acc2,
                                           float xs) {
    uint32_t ph[16], pl[16];
#pragma unroll
    for (int m = 0; m < 16; m++) {
        float a0, a1;
        unpack2(acc2[m], a0, a1);
        __nv_bfloat16 h0, l0, h1, l1;
        split_bf(a0, h0, l0);
        split_bf(a1, h1, l1);
        ph[m] = pack_bf(h0, h1);
        pl[m] = pack_bf(l0, l1);
    }
    uint4* aph = (uint4*)(g_Ah + (size_t)n * A_U32 + tid * 16);
    uint4* apl = (uint4*)(g_Al + (size_t)n * A_U32 + tid * 16);
#pragma unroll
    for (int q = 0; q < 4; q++) {
        aph[q] = make_uint4(ph[4 * q], ph[4 * q + 1], ph[4 * q + 2], ph[4 * q + 3]);
        apl[q] = make_uint4(pl[4 * q], pl[4 * q + 1], pl[4 * q + 2], pl[4 * q + 3]);
    }
    if (tid < IN_C) g_xsum[n * IN_C + tid] = xs;
}

__global__ void __launch_bounds__(128, 6) k_abuild(const float* __restrict__ x,
                                                   const void* __restrict__ ei,
                                                   const float* __restrict__ ea,
                                                   const float* __restrict__ w1,
                                                   const float* __restrict__ b1) {
    int tid = threadIdx.x;
    int is64 = detect64(ei);
    int n0 = blockIdx.x * GNODES;
    int nlocal = min(GNODES, N_NODES - n0);

    unsigned long long w1r2[8];
#pragma unroll
    for (int k = 0; k < 8; k++)
        w1r2[k] = pack2(w1[(2 * k) * HIDDEN + tid], w1[(2 * k + 1) * HIDDEN + tid]);
    float b1v = b1[tid];

    __shared__ int s_off[GNODES + 1];
    __shared__ int s_src[ECAP];
    __shared__ int s_e[ECAP];
    __shared__ __align__(16) float4 s_ea[ECAP][4];
    __shared__ __align__(16) float4 s_xj[ECAP][8];

    if (tid <= nlocal) s_off[tid] = g_off[n0 + tid];
    __syncthreads();

    int pnode = 0;
    while (pnode < nlocal) {
        int estart = s_off[pnode];
        int qnode = pnode;
        while (qnode < nlocal && s_off[qnode + 1] - estart <= ECAP) qnode++;

        if (qnode > pnode) {
            int cnt = s_off[qnode] - estart;
            stage_edges(estart, cnt, tid, is64, ei, ea, x, s_e, s_src, s_ea, s_xj);
            for (int nn = pnode; nn < qnode; nn++) {
                unsigned long long acc2[16];
#pragma unroll
                for (int m = 0; m < 16; m++) acc2[m] = 0ull;
                float xs = 0.f;
                int ls = s_off[nn] - estart, le = s_off[nn + 1] - estart;
                for (int j = ls; j < le; j++)
                    accum_edge(j, tid, w1r2, b1v, acc2, xs, s_ea, s_xj);
                store_node(n0 + nn, tid, acc2, xs);
            }
            pnode = qnode;
        } else {
            int d = s_off[pnode + 1] - estart;
            unsigned long long acc2[16];
#pragma unroll
            for (int m = 0; m < 16; m++) acc2[m] = 0ull;
            float xs = 0.f;
            for (int b = 0; b < d; b += ECAP) {
                int cc = min(d - b, ECAP);
                stage_edges(estart + b, cc, tid, is64, ei, ea, x, s_e, s_src,
                            s_ea, s_xj);
                for (int j = 0; j < cc; j++)
                    accum_edge(j, tid, w1r2, b1v, acc2, xs, s_ea, s_xj);
            }
            store_node(n0 + pnode, tid, acc2, xs);
            pnode++;
        }
    }
}

// ---------------- launch 4 (PROFILED): tcgen05 GEMM (empty if !HAS_TC) ------
__global__ void __launch_bounds__(128) k_gemm_main(const float* __restrict__ x,
                                                   const float* __restrict__ b2,
                                                   const float* __restrict__ rw,
                                                   const float* __restrict__ cb) {
#if HAS_TC
    extern __shared__ __align__(16) char DYN[];
    __shared__ __align__(8) unsigned long long s_mb[2];
    __shared__ uint32_t s_tmem[1];

    int tid = threadIdx.x;
    int wid = tid >> 5, lane = tid & 31;
    int rowbase = blockIdx.x * TCM;

    uint32_t dynbase = smem_u32(DYN);
    uint32_t base = (dynbase + 1023u) & ~1023u;
    char* AB = DYN + (base - dynbase);

    uint32_t mb0 = smem_u32(&s_mb[0]);
    uint32_t mb1 = smem_u32(&s_mb[1]);

    if (tid == 0) {
        mbar_init(mb0, 1);
        mbar_init(mb1, 1);
    }
    if (wid == 0) {
        tc_alloc(smem_u32(&s_tmem[0]), 32);
        tc_relinq();
    }
    __syncthreads();
    uint32_t tmem_d = s_tmem[0];

    uint32_t ph0 = 0, ph1 = 0;

    for (int kt = 0; kt < NK2; kt++) {
        int b = kt & 1;
        uint32_t bufu = base + b * BUFSZ;
        char* buf = AB + b * BUFSZ;

        if (kt >= 2) {
            if (b == 0) { mbar_wait(mb0, ph0); ph0 ^= 1; }
            else        { mbar_wait(mb1, ph1); ph1 ^= 1; }
        }
        __syncthreads();

#pragma unroll
        for (int t = 0; t < 8; t++) {
            int idx = tid + t * 128;
            int row = idx >> 3, q = idx & 7;
            int mg = rowbase + row;
            uint4 vh = make_uint4(0, 0, 0, 0), vl = make_uint4(0, 0, 0, 0);
            if (mg < N_NODES) {
                vh = ((const uint4*)(g_Ah + (size_t)mg * A_U32 + kt * 32))[q];
                vl = ((const uint4*)(g_Al + (size_t)mg * A_U32 + kt * 32))[q];
            }
            uint32_t off = swz128((uint32_t)(row * 128 + q * 16));
            *(uint4*)(buf + off) = vh;
            *(uint4*)(buf + 16384 + off) = vl;
        }
#pragma unroll
        for (int t = 0; t < 2; t++) {
            int idx = tid + t * 128;
            int n = idx >> 3, g = idx & 7;
            int chunk = kt * 2 + (g >> 2);
            int src = chunk * 512 + n * 16 + (g & 3) * 4;
            uint4 vh = *(const uint4*)(g_w2h + src);
            uint4 vl = *(const uint4*)(g_w2l + src);
            uint32_t off = swz128((uint32_t)(n * 128 + g * 16));
            *(uint4*)(buf + 32768 + off) = vh;
            *(uint4*)(buf + 36864 + off) = vl;
        }
        fence_async_shared();
        __syncthreads();

        if (wid == 0 && elect_one()) {
            uint64_t dAh = mk_desc(bufu);
            uint64_t dAl = mk_desc(bufu + 16384);
            uint64_t dWh = mk_desc(bufu + 32768);
            uint64_t dWl = mk_desc(bufu + 36864);
#pragma unroll
            for (int s = 0; s < 4; s++) {
                tc_mma_f16_ss(tmem_d, dAh + 2 * s, dWh + 2 * s, TC_IDESC,
                              !(kt == 0 && s == 0));
                tc_mma_f16_ss(tmem_d, dAh + 2 * s, dWl + 2 * s, TC_IDESC, true);
                tc_mma_f16_ss(tmem_d, dAl + 2 * s, dWh + 2 * s, TC_IDESC, true);
            }
            tc_commit(b == 0 ? mb0 : mb1);
        }
    }

    mbar_wait(mb0, ph0);
    mbar_wait(mb1, ph1);
    tc_fence_after();
    __syncthreads();

    float* B2s = (float*)AB;
    float* RWs = (float*)(AB + 4096);
    float* cbs = (float*)(AB + 8192);
    for (int t = tid; t < 1024; t += 128) {
        B2s[t] = b2[t];
        RWs[t] = rw[t];
    }
    if (tid < 32) cbs[tid] = cb[tid];
    __syncthreads();

    uint32_t dreg[32];
    tc_ld32(dreg, tmem_d);
    tc_wait_ld();

    int mg = rowbase + wid * 32 + lane;
    if (mg < N_NODES) {
        float cnt = (float)(g_off[mg + 1] - g_off[mg]);
        float inv = 1.f / fmaxf(cnt, 1.f);
        float xr[32], xsr[32];
        const float4* xp = (const float4*)(x + (size_t)mg * IN_C);
        const float4* xsp = (const float4*)(g_xsum + (size_t)mg * IN_C);
#pragma unroll
        for (int q = 0; q < 8; q++) {
            float4 v = xp[q];
            xr[4 * q] = v.x; xr[4 * q + 1] = v.y;
            xr[4 * q + 2] = v.z; xr[4 * q + 3] = v.w;
            float4 s = xsp[q];
            xsr[4 * q] = s.x; xsr[4 * q + 1] = s.y;
            xsr[4 * q + 2] = s.z; xsr[4 * q + 3] = s.w;
        }
#pragma unroll 4
        for (int col = 0; col < 32; col++) {
            float e = 0.f, r = 0.f;
#pragma unroll
            for (int i = 0; i < 32; i++) {
                e += xsr[i] * B2s[i * 32 + col];
                r += xr[i] * RWs[i * 32 + col];
            }
            g_h[(size_t)mg * 32 + col] =
                (__uint_as_float(dreg[col]) + e) * inv + r + cbs[col];
        }
    }

    __syncthreads();
    if (wid == 0) tc_dealloc(tmem_d, 32);
#endif
}

// ---------------- launch 5: R11-exact HMMA GEMM (empty if HAS_TC) -----------
__global__ void __launch_bounds__(256) k_gemm_fb(const float* __restrict__ x,
                                                 const float* __restrict__ b2,
                                                 const float* __restrict__ rw,
                                                 const float* __restrict__ cb) {
#if !HAS_TC
    __shared__ __align__(16) unsigned char SMEM[25600];
    __nv_bfloat16* A_hi = (__nv_bfloat16*)SMEM;
    __nv_bfloat16* A_lo = (__nv_bfloat16*)(SMEM + 10240);
    __nv_bfloat16* Wt_hi = (__nv_bfloat16*)(SMEM + 20480);
    __nv_bfloat16* Wt_lo = (__nv_bfloat16*)(SMEM + 23040);
    float* C_s = (float*)SMEM;
    __shared__ float B2s[1024], RWs[1024], cbs[32];

    int tid = threadIdx.x;
    int warp = tid >> 5, lane = tid & 31;
    int gi = lane >> 2, tq = lane & 3;
    int rowbase = blockIdx.x * FBM;

#pragma unroll
    for (int q = 0; q < 4; q++) {
        int id = tid + q * 256;
        B2s[id] = b2[id];
        RWs[id] = rw[id];
    }
    if (tid < 32) cbs[tid] = cb[tid];

    float c[4][4];
#pragma unroll
    for (int j = 0; j < 4; j++)
#pragma unroll
        for (int r = 0; r < 4; r++) c[j][r] = 0.f;

    int lrow = tid >> 1, half = tid & 1;
    bool rowok = (rowbase + lrow) < N_NODES;
    const uint4* ahsrc =
        (const uint4*)(g_Ah + (size_t)(rowbase + lrow) * A_U32) + half * 2;
    const uint4* alsrc =
        (const uint4*)(g_Al + (size_t)(rowbase + lrow) * A_U32) + half * 2;

    uint4 vah[2], val[2];
    uint32_t wrh[2], wrl[2];

#pragma unroll
    for (int q = 0; q < 2; q++) {
        vah[q] = rowok ? ahsrc[q] : make_uint4(0, 0, 0, 0);
        val[q] = rowok ? alsrc[q] : make_uint4(0, 0, 0, 0);
    }
#pragma unroll
    for (int q = 0; q < 2; q++) {
        int id = tid + q * 256;
        wrh[q] = g_w2h[id];
        wrl[q] = g_w2l[id];
    }
    {
        uint4* dh = (uint4*)((uint32_t*)A_hi + lrow * 20 + half * 8);
        uint4* dl = (uint4*)((uint32_t*)A_lo + lrow * 20 + half * 8);
        dh[0] = vah[0]; dh[1] = vah[1];
        dl[0] = val[0]; dl[1] = val[1];
#pragma unroll
        for (int q = 0; q < 2; q++) {
            int id = tid + q * 256;
            int n = id >> 4, kp = id & 15;
            ((uint32_t*)Wt_hi)[n * 20 + kp] = wrh[q];
            ((uint32_t*)Wt_lo)[n * 20 + kp] = wrl[q];
        }
    }
    __syncthreads();

    for (int kt = 0; kt < FNKT; kt++) {
        int ktn = (kt + 1 < FNKT) ? kt + 1 : kt;
#pragma unroll
        for (int q = 0; q < 2; q++) {
            vah[q] = rowok ? ahsrc[ktn * 4 + q] : make_uint4(0, 0, 0, 0);
            val[q] = rowok ? alsrc[ktn * 4 + q] : make_uint4(0, 0, 0, 0);
        }
#pragma unroll
        for (int q = 0; q < 2; q++) {
            int id = tid + q * 256;
            wrh[q] = g_w2h[ktn * 512 + id];
            wrl[q] = g_w2l[ktn * 512 + id];
        }

        int rb = warp * 16;
#pragma unroll
        for (int kk = 0; kk < FBK; kk += 16) {
            const __nv_bfloat16* ah = &A_hi[(rb + gi) * FASTR + kk + 2 * tq];
            const __nv_bfloat16* al = &A_lo[(rb + gi) * FASTR + kk + 2 * tq];
            uint32_t a0h = lds_u32(ah), a1h = lds_u32(ah + 8 * FASTR);
            uint32_t a2h = lds_u32(ah + 8), a3h = lds_u32(ah + 8 * FASTR + 8);
            uint32_t a0l = lds_u32(al), a1l = lds_u32(al + 8 * FASTR);
            uint32_t a2l = lds_u32(al + 8), a3l = lds_u32(al + 8 * FASTR + 8);
#pragma unroll
            for (int j = 0; j < 4; j++) {
                const __nv_bfloat16* bh = &Wt_hi[(j * 8 + gi) * FWSTR + kk + 2 * tq];
                const __nv_bfloat16* bl = &Wt_lo[(j * 8 + gi) * FWSTR + kk + 2 * tq];
                uint32_t b0h = lds_u32(bh), b1h = lds_u32(bh + 8);
                uint32_t b0l = lds_u32(bl), b1l = lds_u32(bl + 8);
                mma16816(c[j], a0h, a1h, a2h, a3h, b0h, b1h);
                mma16816(c[j], a0h, a1h, a2h, a3h, b0l, b1l);
                mma16816(c[j], a0l, a1l, a2l, a3l, b0h, b1h);
            }
        }
        __syncthreads();

        if (kt + 1 < FNKT) {
            uint4* dh = (uint4*)((uint32_t*)A_hi + lrow * 20 + half * 8);
            uint4* dl = (uint4*)((uint32_t*)A_lo + lrow * 20 + half * 8);
            dh[0] = vah[0]; dh[1] = vah[1];
            dl[0] = val[0]; dl[1] = val[1];
#pragma unroll
            for (int q = 0; q < 2; q++) {
                int id = tid + q * 256;
                int n = id >> 4, kp = id & 15;
                ((uint32_t*)Wt_hi)[n * 20 + kp] = wrh[q];
                ((uint32_t*)Wt_lo)[n * 20 + kp] = wrl[q];
            }
        }
        __syncthreads();
    }

    {
        int rb = warp * 16;
#pragma unroll
        for (int j = 0; j < 4; j++) {
            int col = j * 8 + 2 * tq;
            C_s[(rb + gi) * 32 + col] = c[j][0];
            C_s[(rb + gi) * 32 + col + 1] = c[j][1];
            C_s[(rb + gi + 8) * 32 + col] = c[j][2];
            C_s[(rb + gi + 8) * 32 + col + 1] = c[j][3];
        }
    }
    __syncthreads();

    {
        int row = tid >> 1, ch = tid & 1;
        int mg = rowbase + row;
        if (mg < N_NODES) {
            float cnt = (float)(g_off[mg + 1] - g_off[mg]);
            float inv = 1.f / fmaxf(cnt, 1.f);
            const float4* xsp = (const float4*)(g_xsum + (size_t)mg * IN_C);
            const float4* xp = (const float4*)(x + (size_t)mg * IN_C);
            float eacc[16], racc[16];
#pragma unroll
            for (int cjj = 0; cjj < 16; cjj++) { eacc[cjj] = 0.f; racc[cjj] = 0.f; }
#pragma unroll
            for (int i4 = 0; i4 < 8; i4++) {
                float4 xsv = xsp[i4];
                float4 xvv = xp[i4];
                float sv[4] = {xsv.x, xsv.y, xsv.z, xsv.w};
                float vv[4] = {xvv.x, xvv.y, xvv.z, xvv.w};
#pragma unroll
                for (int ii = 0; ii < 4; ii++) {
                    int i = i4 * 4 + ii;
#pragma unroll
                    for (int cjj = 0; cjj < 16; cjj++) {
                        int col = ch * 16 + cjj;
                        eacc[cjj] += sv[ii] * B2s[i * 32 + col];
                        racc[cjj] += vv[ii] * RWs[i * 32 + col];
                    }
                }
            }
#pragma unroll
            for (int cjj = 0; cjj < 16; cjj++) {
                int col = ch * 16 + cjj;
                g_h[(size_t)mg * 32 + col] =
                    (C_s[row * 32 + col] + eacc[cjj]) * inv + racc[cjj] + cbs[col];
            }
        }
    }
#endif
}

// ---------------- BatchNorm statistics (deterministic, no atomics) ----------
__global__ void k_bnstats() {
    int tid = threadIdx.x;  // 256
    int c = tid & 31, g = tid >> 5;
    double s = 0.0, s2 = 0.0;
    for (int row = blockIdx.x * 8 + g; row < N_NODES; row += gridDim.x * 8) {
        float v = g_h[(size_t)row * 32 + c];
        s += (double)v;
        s2 += (double)v * (double)v;
    }
    __shared__ double sh[256], sh2[256];
    sh[tid] = s; sh2[tid] = s2;
    __syncthreads();
    for (int off = 128; off >= 32; off >>= 1) {
        if (tid < off) { sh[tid] += sh[tid + off]; sh2[tid] += sh2[tid + off]; }
        __syncthreads();
    }
    if (tid < 32) {
        g_psum[blockIdx.x][tid] = sh[tid];
        g_psq[blockIdx.x][tid] = sh2[tid];
    }
}

__global__ void k_bnfin(const float* __restrict__ gamma,
                        const float* __restrict__ beta) {
    int c = threadIdx.x;
    if (c < OUT_C) {
        double s = 0.0, s2 = 0.0;
        for (int b = 0; b < BN_BLOCKS; b++) {
            s += g_psum[b][c];
            s2 += g_psq[b][c];
        }
        double mu = s / (double)N_NODES;
        double var = s2 / (double)N_NODES - mu * mu;
        float rstd = (float)rsqrt(var + (double)BN_EPS);
        float sc = rstd * gamma[c];
        g_scale[c] = sc;
        g_shift[c] = beta[c] - (float)mu * sc;
    }
}

// ---------------- output: x + relu(BN(h)) ------------------------------------
__global__ void k_out(const float* __restrict__ x, float* __restrict__ out) {
    int i = blockIdx.x * blockDim.x + threadIdx.x;
    const int total = N_NODES * OUT_C / 4;
    if (i < total) {
        float4 xv = ((const float4*)x)[i];
        float4 hv = ((const float4*)g_h)[i];
        int c = (i & 7) * 4;
        float4 o;
        o.x = xv.x + fmaxf(hv.x * g_scale[c + 0] + g_shift[c + 0], 0.f);
        o.y = xv.y + fmaxf(hv.y * g_scale[c + 1] + g_shift[c + 1], 0.f);
        o.z = xv.z + fmaxf(hv.z * g_scale[c + 2] + g_shift[c + 2], 0.f);
        o.w = xv.w + fmaxf(hv.w * g_scale[c + 3] + g_shift[c + 3], 0.f);
        ((float4*)out)[i] = o;
    }
}

// ---------------- launch -----------------------------------------------------
extern "C" void kernel_launch(void* const* d_in, const int* in_sizes, int n_in,
                              void* d_out, int out_size) {
    const float* x   = (const float*)d_in[0];
    const void*  ei  = d_in[1];               // int32 or int64, self-detected
    const float* ea  = (const float*)d_in[2];
    const float* w1  = (const float*)d_in[3];
    const float* b1  = (const float*)d_in[4];
    const float* w2  = (const float*)d_in[5];
    const float* b2  = (const float*)d_in[6];
    const float* rw  = (const float*)d_in[7];
    const float* cb  = (const float*)d_in[8];
    const float* gam = (const float*)d_in[9];
    const float* bet = (const float*)d_in[10];
    float* out = (float*)d_out;

    cudaFuncSetAttribute(k_gemm_main, cudaFuncAttributeMaxDynamicSharedMemorySize,
                         TC_DYN);

    k_hist<<<512, 256>>>(ei, w2);                    // launch 1
    k_scan_scatter<<<148, 1024>>>(ei);               // launch 2 (fused)
    k_abuild<<<NGROUPS, 128>>>(x, ei, ea, w1, b1);   // launch 3
    k_gemm_main<<<TCGRID, 128, TC_DYN>>>(x, b2, rw, cb);  // launch 4 (profiled)
    k_gemm_fb<<<TCGRID, 256>>>(x, b2, rw, cb);       // launch 5 (null if TC ran)
    k_bnstats<<<BN_BLOCKS, 256>>>();
    k_bnfin<<<1, 32>>>(gam, bet);
    k_out<<<(N_NODES * OUT_C / 4 + 255) / 256, 256>>>(x, out);
}

// round 15
// speedup vs baseline: 1.0642x; 1.0642x over previous
#include <cuda_runtime.h>
#include <cuda_bf16.h>
#include <cstdint>

#define N_NODES 50000
#define N_EDGES 400000
#define IN_C 32
#define OUT_C 32
#define EDGE_DIM 16
#define HIDDEN 128
#define BN_EPS 1e-5f

#define A_COLS (HIDDEN * IN_C)   // 4096
#define A_U32 (A_COLS / 2)       // 2048 packed u32 per node per plane
#define BN_BLOCKS 232

// tcgen05 GEMM tiling
#define TCM 128
#define KT2 64
#define NK2 (A_COLS / KT2)        // 64
#define TCGRID ((N_NODES + TCM - 1) / TCM)   // 391
#define BUFSZ 40960
#define TC_DYN (2 * BUFSZ + 1024)
#define TC_IDESC 0x8080490u       // c=F32, a/b=BF16 K-major, M=128, N=32

// fallback (R11-exact) tiling
#define FBM 128
#define FBK 32
#define FNKT (A_COLS / FBK)       // 128
#define FASTR 40
#define FWSTR 40

// abuild: node-group blocking
#define GNODES 16
#define ECAP 128
#define NGROUPS ((N_NODES + GNODES - 1) / GNODES)   // 3125

// tcgen05 availability: only in arch-specific ('a') device passes
#if defined(__CUDA_ARCH__) && (defined(__CUDA_ARCH_FEAT_SM103_ALL) || \
    defined(__CUDA_ARCH_FEAT_SM100_ALL) || defined(__CUDA_ARCH_FEAT_SM101_ALL) || \
    defined(__CUDA_ARCH_SPECIFIC__))
#define HAS_TC 1
#else
#define HAS_TC 0
#endif

// ---------------- static device scratch (no allocations allowed) ------------
__device__ uint32_t g_Ah[(size_t)N_NODES * A_U32];
__device__ uint32_t g_Al[(size_t)N_NODES * A_U32];
__device__ uint32_t g_w2h[128 * 512];
__device__ uint32_t g_w2l[128 * 512];
__device__ float g_xsum[(size_t)N_NODES * IN_C];
__device__ float g_h[(size_t)N_NODES * OUT_C];
__device__ int   g_hist[N_NODES];   // zero at load; re-zeroed by scan each run
__device__ int   g_off[N_NODES + 1];
__device__ int   g_cursor[N_NODES];
__device__ int   g_perm[N_EDGES];
__device__ int   g_flag;            // scan->scatter release; reset by k_hist
__device__ double g_psum[BN_BLOCKS][OUT_C];
__device__ double g_psq[BN_BLOCKS][OUT_C];
__device__ float g_scale[OUT_C];
__device__ float g_shift[OUT_C];

// ---------------- helpers ----------------------------------------------------
__device__ __forceinline__ void split_bf(float v, __nv_bfloat16& h,
                                         __nv_bfloat16& l) {
    h = __float2bfloat16_rn(v);
    l = __float2bfloat16_rn(v - __bfloat162float(h));
}

__device__ __forceinline__ uint32_t pack_bf(__nv_bfloat16 a, __nv_bfloat16 b) {
    __nv_bfloat162 p;
    p.x = a; p.y = b;
    return *reinterpret_cast<uint32_t*>(&p);
}

__device__ __forceinline__ uint32_t lds_u32(const __nv_bfloat16* p) {
    return *reinterpret_cast<const uint32_t*>(p);
}

__device__ __forceinline__ void mma16816(float c[4], uint32_t a0, uint32_t a1,
                                         uint32_t a2, uint32_t a3, uint32_t b0,
                                         uint32_t b1) {
    asm volatile(
        "mma.sync.aligned.m16n8k16.row.col.f32.bf16.bf16.f32 "
        "{%0,%1,%2,%3}, {%4,%5,%6,%7}, {%8,%9}, {%0,%1,%2,%3};"
        : "+f"(c[0]), "+f"(c[1]), "+f"(c[2]), "+f"(c[3])
        : "r"(a0), "r"(a1), "r"(a2), "r"(a3), "r"(b0), "r"(b1));
}

// packed f32x2 ops (sm_100+)
__device__ __forceinline__ unsigned long long pack2(float a, float b) {
    unsigned long long r;
    asm("mov.b64 %0, {%1, %2};" : "=l"(r) : "f"(a), "f"(b));
    return r;
}
__device__ __forceinline__ void unpack2(unsigned long long v, float& a, float& b) {
    asm("mov.b64 {%0, %1}, %2;" : "=f"(a), "=f"(b) : "l"(v));
}
__device__ __forceinline__ void fma2(unsigned long long& d, unsigned long long a,
                                     unsigned long long b) {
    asm("fma.rn.f32x2 %0, %1, %2, %0;" : "+l"(d) : "l"(a), "l"(b));
}
__device__ __forceinline__ unsigned long long mul2(unsigned long long a,
                                                   unsigned long long b) {
    unsigned long long r;
    asm("mul.rn.f32x2 %0, %1, %2;" : "=l"(r) : "l"(a), "l"(b));
    return r;
}

// self-detecting edge-index load (int32 vs int64 buffer layout)
__device__ __forceinline__ int detect64(const void* ei) {
    const int* p = (const int*)ei;
    return (p[1] == 0) & (p[3] == 0) & (p[5] == 0) & (p[7] == 0);
}
__device__ __forceinline__ int load_idx(const void* ei, int is64, long long elem) {
    int v = is64 ? (int)((const long long*)ei)[elem] : ((const int*)ei)[elem];
    return min(max(v, 0), N_NODES - 1);
}

// ---------------- smem primitives --------------------------------------------
__device__ __forceinline__ uint32_t smem_u32(const void* p) {
    uint32_t a;
    asm("{ .reg .u64 t; cvta.to.shared.u64 t, %1; cvt.u32.u64 %0, t; }"
        : "=r"(a) : "l"(p));
    return a;
}
__device__ __forceinline__ uint32_t swz128(uint32_t off) {
    return off ^ ((off >> 3) & 0x70);
}

#if HAS_TC
__device__ __forceinline__ uint32_t elect_one() {
    uint32_t pred;
    asm volatile("{\n\t.reg .pred p;\n\telect.sync _|p, 0xFFFFFFFF;\n\t"
                 "selp.b32 %0, 1, 0, p;\n\t}" : "=r"(pred));
    return pred;
}
__device__ __forceinline__ void mbar_init(uint32_t a, uint32_t c) {
    asm volatile("mbarrier.init.shared.b64 [%0], %1;" :: "r"(a), "r"(c) : "memory");
}
__device__ __forceinline__ void mbar_wait(uint32_t a, uint32_t par) {
    asm volatile(
        "{\n\t.reg .pred P;\n\t"
        "WL%=:\n\t"
        "mbarrier.try_wait.parity.acquire.cta.shared::cta.b64 P, [%0], %1;\n\t"
        "@!P bra WL%=;\n\t}"
        :: "r"(a), "r"(par) : "memory");
}
__device__ __forceinline__ void tc_alloc(uint32_t slot, uint32_t ncols) {
    asm volatile("tcgen05.alloc.cta_group::1.sync.aligned.shared::cta.b32 [%0], %1;"
                 :: "r"(slot), "r"(ncols) : "memory");
}
__device__ __forceinline__ void tc_relinq() {
    asm volatile("tcgen05.relinquish_alloc_permit.cta_group::1.sync.aligned;");
}
__device__ __forceinline__ void tc_dealloc(uint32_t base, uint32_t ncols) {
    asm volatile("tcgen05.dealloc.cta_group::1.sync.aligned.b32 %0, %1;"
                 :: "r"(base), "r"(ncols));
}
__device__ __forceinline__ void tc_commit(uint32_t mbar) {
    asm volatile(
        "tcgen05.commit.cta_group::1.mbarrier::arrive::one.shared::cluster.b64 [%0];"
        :: "r"(mbar) : "memory");
}
__device__ __forceinline__ void tc_fence_after() {
    asm volatile("tcgen05.fence::after_thread_sync;" ::: "memory");
}
__device__ __forceinline__ void fence_async_shared() {
    asm volatile("fence.proxy.async.shared::cta;" ::: "memory");
}
__device__ __forceinline__ void tc_mma_f16_ss(uint32_t d, uint64_t a, uint64_t b,
                                              uint32_t idesc, bool acc) {
    uint32_t en = acc ? 1u : 0u;
    asm volatile(
        "{\n\t.reg .pred p;\n\tsetp.ne.u32 p, %5, 0;\n\t"
        "tcgen05.mma.cta_group::1.kind::f16 [%0], %1, %2, %3, {%4, %4, %4, %4}, p;\n\t}"
        :: "r"(d), "l"(a), "l"(b), "r"(idesc), "r"(0u), "r"(en) : "memory");
}
__device__ __forceinline__ void tc_ld32(uint32_t* r, uint32_t addr) {
    asm volatile(
        "tcgen05.ld.sync.aligned.32x32b.x32.b32 "
        "{%0,%1,%2,%3,%4,%5,%6,%7,%8,%9,%10,%11,%12,%13,%14,%15,"
        "%16,%17,%18,%19,%20,%21,%22,%23,%24,%25,%26,%27,%28,%29,%30,%31}, [%32];"
        : "=r"(r[0]), "=r"(r[1]), "=r"(r[2]), "=r"(r[3]), "=r"(r[4]), "=r"(r[5]),
          "=r"(r[6]), "=r"(r[7]), "=r"(r[8]), "=r"(r[9]), "=r"(r[10]), "=r"(r[11]),
          "=r"(r[12]), "=r"(r[13]), "=r"(r[14]), "=r"(r[15]), "=r"(r[16]),
          "=r"(r[17]), "=r"(r[18]), "=r"(r[19]), "=r"(r[20]), "=r"(r[21]),
          "=r"(r[22]), "=r"(r[23]), "=r"(r[24]), "=r"(r[25]), "=r"(r[26]),
          "=r"(r[27]), "=r"(r[28]), "=r"(r[29]), "=r"(r[30]), "=r"(r[31])
        : "r"(addr));
}
__device__ __forceinline__ void tc_wait_ld() {
    asm volatile("tcgen05.wait::ld.sync.aligned;" ::: "memory");
}
__device__ __forceinline__ uint64_t mk_desc(uint32_t base) {
    return ((uint64_t)2 << 61) | ((uint64_t)1 << 46) | ((uint64_t)64 << 32) |
           ((uint64_t)1 << 16) | ((uint64_t)(base >> 4) & 0x3FFF);
}
#endif  // HAS_TC

// ---------------- launch 1: histogram + W2 pre-split + flag reset ------------
__global__ void k_hist(const void* __restrict__ ei, const float* __restrict__ w2) {
    if (blockIdx.x == 0 && threadIdx.x == 0) g_flag = 0;
    int is64 = detect64(ei);
    for (int i = blockIdx.x * blockDim.x + threadIdx.x; i < N_EDGES;
         i += gridDim.x * blockDim.x) {
        int dst = load_idx(ei, is64, (long long)N_EDGES + i);
        atomicAdd(&g_hist[dst], 1);
    }
    for (int id = blockIdx.x * blockDim.x + threadIdx.x; id < 128 * 512;
         id += gridDim.x * blockDim.x) {
        int kt = id >> 9, r = id & 511;
        int n = r >> 4, kp = r & 15;
        int k0 = kt * 32 + 2 * kp;
        float v0 = w2[(size_t)k0 * 32 + n];
        float v1 = w2[(size_t)(k0 + 1) * 32 + n];
        __nv_bfloat16 h0, l0, h1, l1;
        split_bf(v0, h0, l0);
        split_bf(v1, h1, l1);
        g_w2h[id] = pack_bf(h0, h1);
        g_w2l[id] = pack_bf(l0, l1);
    }
}

// ---------------- launch 2: fused scan (block 0) + scatter (all blocks) -----
__device__ __forceinline__ int block_excl_scan1024(int v, int* ws) {
    int tid = threadIdx.x;
    int lane = tid & 31, wid = tid >> 5;
    int incl = v;
#pragma unroll
    for (int o = 1; o < 32; o <<= 1) {
        int nv = __shfl_up_sync(0xffffffffu, incl, o);
        if (lane >= o) incl += nv;
    }
    if (lane == 31) ws[wid] = incl;
    __syncthreads();
    if (wid == 0) {
        int wv = ws[lane];
#pragma unroll
        for (int o = 1; o < 32; o <<= 1) {
            int nv = __shfl_up_sync(0xffffffffu, wv, o);
            if (lane >= o) wv += nv;
        }
        ws[lane] = wv;
    }
    __syncthreads();
    int base = (wid > 0) ? ws[wid - 1] : 0;
    return base + incl - v;
}

__global__ void __launch_bounds__(1024) k_scan_scatter(const void* __restrict__ ei) {
    __shared__ int ws[32];
    __shared__ int s_carry;
    int tid = threadIdx.x;

    if (blockIdx.x == 0) {
        if (tid == 0) s_carry = 0;
        __syncthreads();
        for (int base = 0; base < N_NODES; base += 1024) {
            int idx = base + tid;
            int v = (idx < N_NODES) ? g_hist[idx] : 0;
            int ex = block_excl_scan1024(v, ws);
            int c = s_carry;
            if (idx < N_NODES) {
                g_off[idx] = c + ex;
                g_cursor[idx] = c + ex;
                g_hist[idx] = 0;
            }
            __syncthreads();
            if (tid == 1023) s_carry = c + ex + v;
            __syncthreads();
        }
        if (tid == 0) {
            g_off[N_NODES] = N_EDGES;
            __threadfence();
            *(volatile int*)&g_flag = 1;
        }
        __syncthreads();
    } else {
        if (tid == 0) {
            while (*(volatile int*)&g_flag == 0) __nanosleep(200);
        }
        __syncthreads();
        __threadfence();
    }

    int is64 = detect64(ei);
    for (int i = blockIdx.x * 1024 + tid; i < N_EDGES; i += gridDim.x * 1024) {
        int dst = load_idx(ei, is64, (long long)N_EDGES + i);
        int pos = atomicAdd(&g_cursor[dst], 1);
        g_perm[pos] = i;
    }
}

// ---------------- launch 3: A build (R11 exact) ------------------------------
__device__ __forceinline__ void stage_edges(int estart, int cnt, int tid,
                                            int is64, const void* ei,
                                            const float* ea, const float* x,
                                            int* s_e, int* s_src,
                                            float4 (*s_ea)[4],
                                            float4 (*s_xj)[8]) {
    __syncthreads();
    for (int j = tid; j < cnt; j += 128) {
        int e = g_perm[estart + j];
        s_e[j] = e;
        s_src[j] = load_idx(ei, is64, e);
    }
    __syncthreads();
    for (int idx = tid; idx < cnt * 4; idx += 128) {
        int j = idx >> 2, q = idx & 3;
        s_ea[j][q] = ((const float4*)(ea + (size_t)s_e[j] * EDGE_DIM))[q];
    }
    for (int idx = tid; idx < cnt * 8; idx += 128) {
        int j = idx >> 3, q = idx & 7;
        s_xj[j][q] = ((const float4*)(x + (size_t)s_src[j] * IN_C))[q];
    }
    __syncthreads();
}

__device__ __forceinline__ void accum_edge(int j, int tid,
                                           const unsigned long long* w1r2,
                                           float b1v,
                                           unsigned long long* acc2, float& xs,
                                           float4 (*s_ea)[4],
                                           float4 (*s_xj)[8]) {
    float4 e0 = s_ea[j][0], e1 = s_ea[j][1], e2 = s_ea[j][2], e3 = s_ea[j][3];
    unsigned long long h2a = mul2(pack2(e0.x, e0.y), w1r2[0]);
    unsigned long long h2b = mul2(pack2(e0.z, e0.w), w1r2[1]);
    fma2(h2a, pack2(e1.x, e1.y), w1r2[2]);
    fma2(h2b, pack2(e1.z, e1.w), w1r2[3]);
    fma2(h2a, pack2(e2.x, e2.y), w1r2[4]);
    fma2(h2b, pack2(e2.z, e2.w), w1r2[5]);
    fma2(h2a, pack2(e3.x, e3.y), w1r2[6]);
    fma2(h2b, pack2(e3.z, e3.w), w1r2[7]);
    float alo, ahi, blo, bhi;
    unpack2(h2a, alo, ahi);
    unpack2(h2b, blo, bhi);
    float he = fmaxf((alo + blo) + (ahi + bhi) + b1v, 0.f);
    unsigned long long he2 = pack2(he, he);
#pragma unroll
    for (int q = 0; q < 8; q++) {
        float4 xv = s_xj[j][q];
        fma2(acc2[2 * q], he2, pack2(xv.x, xv.y));
        fma2(acc2[2 * q + 1], he2, pack2(xv.z, xv.w));
    }
    if (tid < IN_C) xs += ((const float*)s_xj)[j * 32 + tid];
}

__device__ __forceinline__ void store_node(int n, int tid,
                                           const unsigned long long* acc2,
                                           float xs) {
    uint32_t ph[16], pl[16];
#pragma unroll
    for (int m = 0; m < 16; m++) {
        float a0, a1;
        unpack2(acc2[m], a0, a1);
        __nv_bfloat16 h0, l0, h1, l1;
        split_bf(a0, h0, l0);
        split_bf(a1, h1, l1);
        ph[m] = pack_bf(h0, h1);
        pl[m] = pack_bf(l0, l1);
    }
    uint4* aph = (uint4*)(g_Ah + (size_t)n * A_U32 + tid * 16);
    uint4* apl = (uint4*)(g_Al + (size_t)n * A_U32 + tid * 16);
#pragma unroll
    for (int q = 0; q < 4; q++) {
        aph[q] = make_uint4(ph[4 * q], ph[4 * q + 1], ph[4 * q + 2], ph[4 * q + 3]);
        apl[q] = make_uint4(pl[4 * q], pl[4 * q + 1], pl[4 * q + 2], pl[4 * q + 3]);
    }
    if (tid < IN_C) g_xsum[n * IN_C + tid] = xs;
}

__global__ void __launch_bounds__(128, 6) k_abuild(const float* __restrict__ x,
                                                   const void* __restrict__ ei,
                                                   const float* __restrict__ ea,
                                                   const float* __restrict__ w1,
                                                   const float* __restrict__ b1) {
    int tid = threadIdx.x;
    int is64 = detect64(ei);
    int n0 = blockIdx.x * GNODES;
    int nlocal = min(GNODES, N_NODES - n0);

    unsigned long long w1r2[8];
#pragma unroll
    for (int k = 0; k < 8; k++)
        w1r2[k] = pack2(w1[(2 * k) * HIDDEN + tid], w1[(2 * k + 1) * HIDDEN + tid]);
    float b1v = b1[tid];

    __shared__ int s_off[GNODES + 1];
    __shared__ int s_src[ECAP];
    __shared__ int s_e[ECAP];
    __shared__ __align__(16) float4 s_ea[ECAP][4];
    __shared__ __align__(16) float4 s_xj[ECAP][8];

    if (tid <= nlocal) s_off[tid] = g_off[n0 + tid];
    __syncthreads();

    int pnode = 0;
    while (pnode < nlocal) {
        int estart = s_off[pnode];
        int qnode = pnode;
        while (qnode < nlocal && s_off[qnode + 1] - estart <= ECAP) qnode++;

        if (qnode > pnode) {
            int cnt = s_off[qnode] - estart;
            stage_edges(estart, cnt, tid, is64, ei, ea, x, s_e, s_src, s_ea, s_xj);
            for (int nn = pnode; nn < qnode; nn++) {
                unsigned long long acc2[16];
#pragma unroll
                for (int m = 0; m < 16; m++) acc2[m] = 0ull;
                float xs = 0.f;
                int ls = s_off[nn] - estart, le = s_off[nn + 1] - estart;
                for (int j = ls; j < le; j++)
                    accum_edge(j, tid, w1r2, b1v, acc2, xs, s_ea, s_xj);
                store_node(n0 + nn, tid, acc2, xs);
            }
            pnode = qnode;
        } else {
            int d = s_off[pnode + 1] - estart;
            unsigned long long acc2[16];
#pragma unroll
            for (int m = 0; m < 16; m++) acc2[m] = 0ull;
            float xs = 0.f;
            for (int b = 0; b < d; b += ECAP) {
                int cc = min(d - b, ECAP);
                stage_edges(estart + b, cc, tid, is64, ei, ea, x, s_e, s_src,
                            s_ea, s_xj);
                for (int j = 0; j < cc; j++)
                    accum_edge(j, tid, w1r2, b1v, acc2, xs, s_ea, s_xj);
            }
            store_node(n0 + pnode, tid, acc2, xs);
            pnode++;
        }
    }
}

// ---------------- launch 4 (PROFILED): tcgen05 GEMM, 256 staging threads ----
__global__ void __launch_bounds__(256) k_gemm_main(const float* __restrict__ x,
                                                   const float* __restrict__ b2,
                                                   const float* __restrict__ rw,
                                                   const float* __restrict__ cb) {
#if HAS_TC
    extern __shared__ __align__(16) char DYN[];
    __shared__ __align__(8) unsigned long long s_mb[2];
    __shared__ uint32_t s_tmem[1];

    int tid = threadIdx.x;
    int wid = tid >> 5, lane = tid & 31;
    int rowbase = blockIdx.x * TCM;

    uint32_t dynbase = smem_u32(DYN);
    uint32_t base = (dynbase + 1023u) & ~1023u;
    char* AB = DYN + (base - dynbase);

    uint32_t mb0 = smem_u32(&s_mb[0]);
    uint32_t mb1 = smem_u32(&s_mb[1]);

    if (tid == 0) {
        mbar_init(mb0, 1);
        mbar_init(mb1, 1);
    }
    if (wid == 0) {
        tc_alloc(smem_u32(&s_tmem[0]), 32);
        tc_relinq();
    }
    __syncthreads();
    uint32_t tmem_d = s_tmem[0];

    uint32_t ph0 = 0, ph1 = 0;

    for (int kt = 0; kt < NK2; kt++) {
        int b = kt & 1;
        uint32_t bufu = base + b * BUFSZ;
        char* buf = AB + b * BUFSZ;

        if (kt >= 2) {
            if (b == 0) { mbar_wait(mb0, ph0); ph0 ^= 1; }
            else        { mbar_wait(mb1, ph1); ph1 ^= 1; }
        }
        __syncthreads();

        // ---- stage A_hi / A_lo tiles: 128 rows x 128B, SW128 (256 thr) ----
#pragma unroll
        for (int t = 0; t < 4; t++) {
            int idx = tid + t * 256;           // 0..1023
            int row = idx >> 3, q = idx & 7;
            int mg = rowbase + row;
            uint4 vh = make_uint4(0, 0, 0, 0), vl = make_uint4(0, 0, 0, 0);
            if (mg < N_NODES) {
                vh = ((const uint4*)(g_Ah + (size_t)mg * A_U32 + kt * 32))[q];
                vl = ((const uint4*)(g_Al + (size_t)mg * A_U32 + kt * 32))[q];
            }
            uint32_t off = swz128((uint32_t)(row * 128 + q * 16));
            *(uint4*)(buf + off) = vh;
            *(uint4*)(buf + 16384 + off) = vl;
        }
        // ---- stage W_hi / W_lo tiles: 32 rows x 128B, SW128 (256 thr) ----
        {
            int idx = tid;                     // 0..255
            int n = idx >> 3, g = idx & 7;
            int chunk = kt * 2 + (g >> 2);
            int src = chunk * 512 + n * 16 + (g & 3) * 4;
            uint4 vh = *(const uint4*)(g_w2h + src);
            uint4 vl = *(const uint4*)(g_w2l + src);
            uint32_t off = swz128((uint32_t)(n * 128 + g * 16));
            *(uint4*)(buf + 32768 + off) = vh;
            *(uint4*)(buf + 36864 + off) = vl;
        }
        fence_async_shared();
        __syncthreads();

        if (wid == 0 && elect_one()) {
            uint64_t dAh = mk_desc(bufu);
            uint64_t dAl = mk_desc(bufu + 16384);
            uint64_t dWh = mk_desc(bufu + 32768);
            uint64_t dWl = mk_desc(bufu + 36864);
#pragma unroll
            for (int s = 0; s < 4; s++) {
                tc_mma_f16_ss(tmem_d, dAh + 2 * s, dWh + 2 * s, TC_IDESC,
                              !(kt == 0 && s == 0));
                tc_mma_f16_ss(tmem_d, dAh + 2 * s, dWl + 2 * s, TC_IDESC, true);
                tc_mma_f16_ss(tmem_d, dAl + 2 * s, dWh + 2 * s, TC_IDESC, true);
            }
            tc_commit(b == 0 ? mb0 : mb1);
        }
    }

    mbar_wait(mb0, ph0);
    mbar_wait(mb1, ph1);
    tc_fence_after();
    __syncthreads();

    float* B2s = (float*)AB;
    float* RWs = (float*)(AB + 4096);
    float* cbs = (float*)(AB + 8192);
    for (int t = tid; t < 1024; t += 256) {
        B2s[t] = b2[t];
        RWs[t] = rw[t];
    }
    if (tid < 32) cbs[tid] = cb[tid];
    __syncthreads();

    // TMEM D read: only warps 0-3 own the 128 TMEM lanes
    if (wid < 4) {
        uint32_t dreg[32];
        tc_ld32(dreg, tmem_d);
        tc_wait_ld();

        int mg = rowbase + wid * 32 + lane;
        if (mg < N_NODES) {
            float cnt = (float)(g_off[mg + 1] - g_off[mg]);
            float inv = 1.f / fmaxf(cnt, 1.f);
            float xr[32], xsr[32];
            const float4* xp = (const float4*)(x + (size_t)mg * IN_C);
            const float4* xsp = (const float4*)(g_xsum + (size_t)mg * IN_C);
#pragma unroll
            for (int q = 0; q < 8; q++) {
                float4 v = xp[q];
                xr[4 * q] = v.x; xr[4 * q + 1] = v.y;
                xr[4 * q + 2] = v.z; xr[4 * q + 3] = v.w;
                float4 s = xsp[q];
                xsr[4 * q] = s.x; xsr[4 * q + 1] = s.y;
                xsr[4 * q + 2] = s.z; xsr[4 * q + 3] = s.w;
            }
#pragma unroll 4
            for (int col = 0; col < 32; col++) {
                float e = 0.f, r = 0.f;
#pragma unroll
                for (int i = 0; i < 32; i++) {
                    e += xsr[i] * B2s[i * 32 + col];
                    r += xr[i] * RWs[i * 32 + col];
                }
                g_h[(size_t)mg * 32 + col] =
                    (__uint_as_float(dreg[col]) + e) * inv + r + cbs[col];
            }
        }
    }

    __syncthreads();
    if (wid == 0) tc_dealloc(tmem_d, 32);
#endif
}

// ---------------- launch 5: R11-exact HMMA GEMM (empty if HAS_TC) -----------
__global__ void __launch_bounds__(256) k_gemm_fb(const float* __restrict__ x,
                                                 const float* __restrict__ b2,
                                                 const float* __restrict__ rw,
                                                 const float* __restrict__ cb) {
#if !HAS_TC
    __shared__ __align__(16) unsigned char SMEM[25600];
    __nv_bfloat16* A_hi = (__nv_bfloat16*)SMEM;
    __nv_bfloat16* A_lo = (__nv_bfloat16*)(SMEM + 10240);
    __nv_bfloat16* Wt_hi = (__nv_bfloat16*)(SMEM + 20480);
    __nv_bfloat16* Wt_lo = (__nv_bfloat16*)(SMEM + 23040);
    float* C_s = (float*)SMEM;
    __shared__ float B2s[1024], RWs[1024], cbs[32];

    int tid = threadIdx.x;
    int warp = tid >> 5, lane = tid & 31;
    int gi = lane >> 2, tq = lane & 3;
    int rowbase = blockIdx.x * FBM;

#pragma unroll
    for (int q = 0; q < 4; q++) {
        int id = tid + q * 256;
        B2s[id] = b2[id];
        RWs[id] = rw[id];
    }
    if (tid < 32) cbs[tid] = cb[tid];

    float c[4][4];
#pragma unroll
    for (int j = 0; j < 4; j++)
#pragma unroll
        for (int r = 0; r < 4; r++) c[j][r] = 0.f;

    int lrow = tid >> 1, half = tid & 1;
    bool rowok = (rowbase + lrow) < N_NODES;
    const uint4* ahsrc =
        (const uint4*)(g_Ah + (size_t)(rowbase + lrow) * A_U32) + half * 2;
    const uint4* alsrc =
        (const uint4*)(g_Al + (size_t)(rowbase + lrow) * A_U32) + half * 2;

    uint4 vah[2], val[2];
    uint32_t wrh[2], wrl[2];

#pragma unroll
    for (int q = 0; q < 2; q++) {
        vah[q] = rowok ? ahsrc[q] : make_uint4(0, 0, 0, 0);
        val[q] = rowok ? alsrc[q] : make_uint4(0, 0, 0, 0);
    }
#pragma unroll
    for (int q = 0; q < 2; q++) {
        int id = tid + q * 256;
        wrh[q] = g_w2h[id];
        wrl[q] = g_w2l[id];
    }
    {
        uint4* dh = (uint4*)((uint32_t*)A_hi + lrow * 20 + half * 8);
        uint4* dl = (uint4*)((uint32_t*)A_lo + lrow * 20 + half * 8);
        dh[0] = vah[0]; dh[1] = vah[1];
        dl[0] = val[0]; dl[1] = val[1];
#pragma unroll
        for (int q = 0; q < 2; q++) {
            int id = tid + q * 256;
            int n = id >> 4, kp = id & 15;
            ((uint32_t*)Wt_hi)[n * 20 + kp] = wrh[q];
            ((uint32_t*)Wt_lo)[n * 20 + kp] = wrl[q];
        }
    }
    __syncthreads();

    for (int kt = 0; kt < FNKT; kt++) {
        int ktn = (kt + 1 < FNKT) ? kt + 1 : kt;
#pragma unroll
        for (int q = 0; q < 2; q++) {
            vah[q] = rowok ? ahsrc[ktn * 4 + q] : make_uint4(0, 0, 0, 0);
            val[q] = rowok ? alsrc[ktn * 4 + q] : make_uint4(0, 0, 0, 0);
        }
#pragma unroll
        for (int q = 0; q < 2; q++) {
            int id = tid + q * 256;
            wrh[q] = g_w2h[ktn * 512 + id];
            wrl[q] = g_w2l[ktn * 512 + id];
        }

        int rb = warp * 16;
#pragma unroll
        for (int kk = 0; kk < FBK; kk += 16) {
            const __nv_bfloat16* ah = &A_hi[(rb + gi) * FASTR + kk + 2 * tq];
            const __nv_bfloat16* al = &A_lo[(rb + gi) * FASTR + kk + 2 * tq];
            uint32_t a0h = lds_u32(ah), a1h = lds_u32(ah + 8 * FASTR);
            uint32_t a2h = lds_u32(ah + 8), a3h = lds_u32(ah + 8 * FASTR + 8);
            uint32_t a0l = lds_u32(al), a1l = lds_u32(al + 8 * FASTR);
            uint32_t a2l = lds_u32(al + 8), a3l = lds_u32(al + 8 * FASTR + 8);
#pragma unroll
            for (int j = 0; j < 4; j++) {
                const __nv_bfloat16* bh = &Wt_hi[(j * 8 + gi) * FWSTR + kk + 2 * tq];
                const __nv_bfloat16* bl = &Wt_lo[(j * 8 + gi) * FWSTR + kk + 2 * tq];
                uint32_t b0h = lds_u32(bh), b1h = lds_u32(bh + 8);
                uint32_t b0l = lds_u32(bl), b1l = lds_u32(bl + 8);
                mma16816(c[j], a0h, a1h, a2h, a3h, b0h, b1h);
                mma16816(c[j], a0h, a1h, a2h, a3h, b0l, b1l);
                mma16816(c[j], a0l, a1l, a2l, a3l, b0h, b1h);
            }
        }
        __syncthreads();

        if (kt + 1 < FNKT) {
            uint4* dh = (uint4*)((uint32_t*)A_hi + lrow * 20 + half * 8);
            uint4* dl = (uint4*)((uint32_t*)A_lo + lrow * 20 + half * 8);
            dh[0] = vah[0]; dh[1] = vah[1];
            dl[0] = val[0]; dl[1] = val[1];
#pragma unroll
            for (int q = 0; q < 2; q++) {
                int id = tid + q * 256;
                int n = id >> 4, kp = id & 15;
                ((uint32_t*)Wt_hi)[n * 20 + kp] = wrh[q];
                ((uint32_t*)Wt_lo)[n * 20 + kp] = wrl[q];
            }
        }
        __syncthreads();
    }

    {
        int rb = warp * 16;
#pragma unroll
        for (int j = 0; j < 4; j++) {
            int col = j * 8 + 2 * tq;
            C_s[(rb + gi) * 32 + col] = c[j][0];
            C_s[(rb + gi) * 32 + col + 1] = c[j][1];
            C_s[(rb + gi + 8) * 32 + col] = c[j][2];
            C_s[(rb + gi + 8) * 32 + col + 1] = c[j][3];
        }
    }
    __syncthreads();

    {
        int row = tid >> 1, ch = tid & 1;
        int mg = rowbase + row;
        if (mg < N_NODES) {
            float cnt = (float)(g_off[mg + 1] - g_off[mg]);
            float inv = 1.f / fmaxf(cnt, 1.f);
            const float4* xsp = (const float4*)(g_xsum + (size_t)mg * IN_C);
            const float4* xp = (const float4*)(x + (size_t)mg * IN_C);
            float eacc[16], racc[16];
#pragma unroll
            for (int cjj = 0; cjj < 16; cjj++) { eacc[cjj] = 0.f; racc[cjj] = 0.f; }
#pragma unroll
            for (int i4 = 0; i4 < 8; i4++) {
                float4 xsv = xsp[i4];
                float4 xvv = xp[i4];
                float sv[4] = {xsv.x, xsv.y, xsv.z, xsv.w};
                float vv[4] = {xvv.x, xvv.y, xvv.z, xvv.w};
#pragma unroll
                for (int ii = 0; ii < 4; ii++) {
                    int i = i4 * 4 + ii;
#pragma unroll
                    for (int cjj = 0; cjj < 16; cjj++) {
                        int col = ch * 16 + cjj;
                        eacc[cjj] += sv[ii] * B2s[i * 32 + col];
                        racc[cjj] += vv[ii] * RWs[i * 32 + col];
                    }
                }
            }
#pragma unroll
            for (int cjj = 0; cjj < 16; cjj++) {
                int col = ch * 16 + cjj;
                g_h[(size_t)mg * 32 + col] =
                    (C_s[row * 32 + col] + eacc[cjj]) * inv + racc[cjj] + cbs[col];
            }
        }
    }
#endif
}

// ---------------- BatchNorm statistics (deterministic, no atomics) ----------
__global__ void k_bnstats() {
    int tid = threadIdx.x;  // 256
    int c = tid & 31, g = tid >> 5;
    double s = 0.0, s2 = 0.0;
    for (int row = blockIdx.x * 8 + g; row < N_NODES; row += gridDim.x * 8) {
        float v = g_h[(size_t)row * 32 + c];
        s += (double)v;
        s2 += (double)v * (double)v;
    }
    __shared__ double sh[256], sh2[256];
    sh[tid] = s; sh2[tid] = s2;
    __syncthreads();
    for (int off = 128; off >= 32; off >>= 1) {
        if (tid < off) { sh[tid] += sh[tid + off]; sh2[tid] += sh2[tid + off]; }
        __syncthreads();
    }
    if (tid < 32) {
        g_psum[blockIdx.x][tid] = sh[tid];
        g_psq[blockIdx.x][tid] = sh2[tid];
    }
}

__global__ void k_bnfin(const float* __restrict__ gamma,
                        const float* __restrict__ beta) {
    int c = threadIdx.x;
    if (c < OUT_C) {
        double s = 0.0, s2 = 0.0;
        for (int b = 0; b < BN_BLOCKS; b++) {
            s += g_psum[b][c];
            s2 += g_psq[b][c];
        }
        double mu = s / (double)N_NODES;
        double var = s2 / (double)N_NODES - mu * mu;
        float rstd = (float)rsqrt(var + (double)BN_EPS);
        float sc = rstd * gamma[c];
        g_scale[c] = sc;
        g_shift[c] = beta[c] - (float)mu * sc;
    }
}

// ---------------- output: x + relu(BN(h)) ------------------------------------
__global__ void k_out(const float* __restrict__ x, float* __restrict__ out) {
    int i = blockIdx.x * blockDim.x + threadIdx.x;
    const int total = N_NODES * OUT_C / 4;
    if (i < total) {
        float4 xv = ((const float4*)x)[i];
        float4 hv = ((const float4*)g_h)[i];
        int c = (i & 7) * 4;
        float4 o;
        o.x = xv.x + fmaxf(hv.x * g_scale[c + 0] + g_shift[c + 0], 0.f);
        o.y = xv.y + fmaxf(hv.y * g_scale[c + 1] + g_shift[c + 1], 0.f);
        o.z = xv.z + fmaxf(hv.z * g_scale[c + 2] + g_shift[c + 2], 0.f);
        o.w = xv.w + fmaxf(hv.w * g_scale[c + 3] + g_shift[c + 3], 0.f);
        ((float4*)out)[i] = o;
    }
}

// ---------------- launch -----------------------------------------------------
extern "C" void kernel_launch(void* const* d_in, const int* in_sizes, int n_in,
                              void* d_out, int out_size) {
    const float* x   = (const float*)d_in[0];
    const void*  ei  = d_in[1];               // int32 or int64, self-detected
    const float* ea  = (const float*)d_in[2];
    const float* w1  = (const float*)d_in[3];
    const float* b1  = (const float*)d_in[4];
    const float* w2  = (const float*)d_in[5];
    const float* b2  = (const float*)d_in[6];
    const float* rw  = (const float*)d_in[7];
    const float* cb  = (const float*)d_in[8];
    const float* gam = (const float*)d_in[9];
    const float* bet = (const float*)d_in[10];
    float* out = (float*)d_out;

    cudaFuncSetAttribute(k_gemm_main, cudaFuncAttributeMaxDynamicSharedMemorySize,
                         TC_DYN);

    k_hist<<<512, 256>>>(ei, w2);                    // launch 1
    k_scan_scatter<<<148, 1024>>>(ei);               // launch 2 (fused)
    k_abuild<<<NGROUPS, 128>>>(x, ei, ea, w1, b1);   // launch 3
    k_gemm_main<<<TCGRID, 256, TC_DYN>>>(x, b2, rw, cb);  // launch 4 (profiled)
    k_gemm_fb<<<TCGRID, 256>>>(x, b2, rw, cb);       // launch 5 (null if TC ran)
    k_bnstats<<<BN_BLOCKS, 256>>>();
    k_bnfin<<<1, 32>>>(gam, bet);
    k_out<<<(N_NODES * OUT_C / 4 + 255) / 256, 256>>>(x, out);
}

// round 16
// speedup vs baseline: 1.1734x; 1.1026x over previous
#include <cuda_runtime.h>
#include <cuda_bf16.h>
#include <cstdint>

#define N_NODES 50000
#define N_EDGES 400000
#define IN_C 32
#define OUT_C 32
#define EDGE_DIM 16
#define HIDDEN 128
#define BN_EPS 1e-5f

#define A_COLS (HIDDEN * IN_C)   // 4096
#define A_U32 (A_COLS / 2)       // 2048 packed u32 per node per plane
#define BN_BLOCKS 232

// tcgen05 GEMM tiling
#define TCM 128
#define KT2 64
#define NK2 (A_COLS / KT2)        // 64
#define TCGRID ((N_NODES + TCM - 1) / TCM)   // 391
#define BUFSZ 40960
#define TC_DYN (2 * BUFSZ + 1024)
#define TC_IDESC 0x8080490u       // c=F32, a/b=BF16 K-major, M=128, N=32

// fallback (R11-exact) tiling
#define FBM 128
#define FBK 32
#define FNKT (A_COLS / FBK)       // 128
#define FASTR 40
#define FWSTR 40

// abuild: node-group blocking
#define GNODES 16
#define ECAP 128
#define NGROUPS ((N_NODES + GNODES - 1) / GNODES)   // 3125

// tcgen05 availability: only in arch-specific ('a') device passes
#if defined(__CUDA_ARCH__) && (defined(__CUDA_ARCH_FEAT_SM103_ALL) || \
    defined(__CUDA_ARCH_FEAT_SM100_ALL) || defined(__CUDA_ARCH_FEAT_SM101_ALL) || \
    defined(__CUDA_ARCH_SPECIFIC__))
#define HAS_TC 1
#else
#define HAS_TC 0
#endif

// ---------------- static device scratch (no allocations allowed) ------------
__device__ uint32_t g_Ah[(size_t)N_NODES * A_U32];
__device__ uint32_t g_Al[(size_t)N_NODES * A_U32];
__device__ uint32_t g_w2h[128 * 512];
__device__ uint32_t g_w2l[128 * 512];
__device__ float g_xsum[(size_t)N_NODES * IN_C];
__device__ float g_h[(size_t)N_NODES * OUT_C];
__device__ int   g_hist[N_NODES];   // zero at load; re-zeroed by scan each run
__device__ int   g_off[N_NODES + 1];
__device__ int   g_cursor[N_NODES];
__device__ int   g_perm[N_EDGES];
__device__ int   g_flag;            // scan->scatter release; reset by k_hist
__device__ double g_psum[BN_BLOCKS][OUT_C];
__device__ double g_psq[BN_BLOCKS][OUT_C];
__device__ float g_scale[OUT_C];
__device__ float g_shift[OUT_C];

// ---------------- helpers ----------------------------------------------------
__device__ __forceinline__ void split_bf(float v, __nv_bfloat16& h,
                                         __nv_bfloat16& l) {
    h = __float2bfloat16_rn(v);
    l = __float2bfloat16_rn(v - __bfloat162float(h));
}

__device__ __forceinline__ uint32_t pack_bf(__nv_bfloat16 a, __nv_bfloat16 b) {
    __nv_bfloat162 p;
    p.x = a; p.y = b;
    return *reinterpret_cast<uint32_t*>(&p);
}

__device__ __forceinline__ uint32_t lds_u32(const __nv_bfloat16* p) {
    return *reinterpret_cast<const uint32_t*>(p);
}

__device__ __forceinline__ void mma16816(float c[4], uint32_t a0, uint32_t a1,
                                         uint32_t a2, uint32_t a3, uint32_t b0,
                                         uint32_t b1) {
    asm volatile(
        "mma.sync.aligned.m16n8k16.row.col.f32.bf16.bf16.f32 "
        "{%0,%1,%2,%3}, {%4,%5,%6,%7}, {%8,%9}, {%0,%1,%2,%3};"
        : "+f"(c[0]), "+f"(c[1]), "+f"(c[2]), "+f"(c[3])
        : "r"(a0), "r"(a1), "r"(a2), "r"(a3), "r"(b0), "r"(b1));
}

// packed f32x2 ops (sm_100+)
__device__ __forceinline__ unsigned long long pack2(float a, float b) {
    unsigned long long r;
    asm("mov.b64 %0, {%1, %2};" : "=l"(r) : "f"(a), "f"(b));
    return r;
}
__device__ __forceinline__ void unpack2(unsigned long long v, float& a, float& b) {
    asm("mov.b64 {%0, %1}, %2;" : "=f"(a), "=f"(b) : "l"(v));
}
__device__ __forceinline__ void fma2(unsigned long long& d, unsigned long long a,
                                     unsigned long long b) {
    asm("fma.rn.f32x2 %0, %1, %2, %0;" : "+l"(d) : "l"(a), "l"(b));
}
__device__ __forceinline__ unsigned long long mul2(unsigned long long a,
                                                   unsigned long long b) {
    unsigned long long r;
    asm("mul.rn.f32x2 %0, %1, %2;" : "=l"(r) : "l"(a), "l"(b));
    return r;
}

// self-detecting edge-index load (int32 vs int64 buffer layout)
__device__ __forceinline__ int detect64(const void* ei) {
    const int* p = (const int*)ei;
    return (p[1] == 0) & (p[3] == 0) & (p[5] == 0) & (p[7] == 0);
}
__device__ __forceinline__ int load_idx(const void* ei, int is64, long long elem) {
    int v = is64 ? (int)((const long long*)ei)[elem] : ((const int*)ei)[elem];
    return min(max(v, 0), N_NODES - 1);
}

// ---------------- smem primitives --------------------------------------------
__device__ __forceinline__ uint32_t smem_u32(const void* p) {
    uint32_t a;
    asm("{ .reg .u64 t; cvta.to.shared.u64 t, %1; cvt.u32.u64 %0, t; }"
        : "=r"(a) : "l"(p));
    return a;
}
__device__ __forceinline__ uint32_t swz128(uint32_t off) {
    return off ^ ((off >> 3) & 0x70);
}

// cp.async 16B copy with zero-fill when invalid
__device__ __forceinline__ void cp16(uint32_t dst, const void* src, bool valid) {
    int sz = valid ? 16 : 0;
    asm volatile("cp.async.cg.shared.global [%0], [%1], 16, %2;"
                 :: "r"(dst), "l"(src), "r"(sz) : "memory");
}
__device__ __forceinline__ void cp_commit() {
    asm volatile("cp.async.commit_group;" ::: "memory");
}
__device__ __forceinline__ void cp_wait0() {
    asm volatile("cp.async.wait_group 0;" ::: "memory");
}
__device__ __forceinline__ void cp_wait1() {
    asm volatile("cp.async.wait_group 1;" ::: "memory");
}

#if HAS_TC
__device__ __forceinline__ uint32_t elect_one() {
    uint32_t pred;
    asm volatile("{\n\t.reg .pred p;\n\telect.sync _|p, 0xFFFFFFFF;\n\t"
                 "selp.b32 %0, 1, 0, p;\n\t}" : "=r"(pred));
    return pred;
}
__device__ __forceinline__ void mbar_init(uint32_t a, uint32_t c) {
    asm volatile("mbarrier.init.shared.b64 [%0], %1;" :: "r"(a), "r"(c) : "memory");
}
__device__ __forceinline__ void mbar_wait(uint32_t a, uint32_t par) {
    asm volatile(
        "{\n\t.reg .pred P;\n\t"
        "WL%=:\n\t"
        "mbarrier.try_wait.parity.acquire.cta.shared::cta.b64 P, [%0], %1;\n\t"
        "@!P bra WL%=;\n\t}"
        :: "r"(a), "r"(par) : "memory");
}
__device__ __forceinline__ void tc_alloc(uint32_t slot, uint32_t ncols) {
    asm volatile("tcgen05.alloc.cta_group::1.sync.aligned.shared::cta.b32 [%0], %1;"
                 :: "r"(slot), "r"(ncols) : "memory");
}
__device__ __forceinline__ void tc_relinq() {
    asm volatile("tcgen05.relinquish_alloc_permit.cta_group::1.sync.aligned;");
}
__device__ __forceinline__ void tc_dealloc(uint32_t base, uint32_t ncols) {
    asm volatile("tcgen05.dealloc.cta_group::1.sync.aligned.b32 %0, %1;"
                 :: "r"(base), "r"(ncols));
}
__device__ __forceinline__ void tc_commit(uint32_t mbar) {
    asm volatile(
        "tcgen05.commit.cta_group::1.mbarrier::arrive::one.shared::cluster.b64 [%0];"
        :: "r"(mbar) : "memory");
}
__device__ __forceinline__ void tc_fence_after() {
    asm volatile("tcgen05.fence::after_thread_sync;" ::: "memory");
}
__device__ __forceinline__ void fence_async_shared() {
    asm volatile("fence.proxy.async.shared::cta;" ::: "memory");
}
__device__ __forceinline__ void tc_mma_f16_ss(uint32_t d, uint64_t a, uint64_t b,
                                              uint32_t idesc, bool acc) {
    uint32_t en = acc ? 1u : 0u;
    asm volatile(
        "{\n\t.reg .pred p;\n\tsetp.ne.u32 p, %5, 0;\n\t"
        "tcgen05.mma.cta_group::1.kind::f16 [%0], %1, %2, %3, {%4, %4, %4, %4}, p;\n\t}"
        :: "r"(d), "l"(a), "l"(b), "r"(idesc), "r"(0u), "r"(en) : "memory");
}
__device__ __forceinline__ void tc_ld32(uint32_t* r, uint32_t addr) {
    asm volatile(
        "tcgen05.ld.sync.aligned.32x32b.x32.b32 "
        "{%0,%1,%2,%3,%4,%5,%6,%7,%8,%9,%10,%11,%12,%13,%14,%15,"
        "%16,%17,%18,%19,%20,%21,%22,%23,%24,%25,%26,%27,%28,%29,%30,%31}, [%32];"
        : "=r"(r[0]), "=r"(r[1]), "=r"(r[2]), "=r"(r[3]), "=r"(r[4]), "=r"(r[5]),
          "=r"(r[6]), "=r"(r[7]), "=r"(r[8]), "=r"(r[9]), "=r"(r[10]), "=r"(r[11]),
          "=r"(r[12]), "=r"(r[13]), "=r"(r[14]), "=r"(r[15]), "=r"(r[16]),
          "=r"(r[17]), "=r"(r[18]), "=r"(r[19]), "=r"(r[20]), "=r"(r[21]),
          "=r"(r[22]), "=r"(r[23]), "=r"(r[24]), "=r"(r[25]), "=r"(r[26]),
          "=r"(r[27]), "=r"(r[28]), "=r"(r[29]), "=r"(r[30]), "=r"(r[31])
        : "r"(addr));
}
__device__ __forceinline__ void tc_wait_ld() {
    asm volatile("tcgen05.wait::ld.sync.aligned;" ::: "memory");
}
__device__ __forceinline__ uint64_t mk_desc(uint32_t base) {
    return ((uint64_t)2 << 61) | ((uint64_t)1 << 46) | ((uint64_t)64 << 32) |
           ((uint64_t)1 << 16) | ((uint64_t)(base >> 4) & 0x3FFF);
}
#endif  // HAS_TC

// ---------------- launch 1: histogram + W2 pre-split + flag reset ------------
__global__ void k_hist(const void* __restrict__ ei, const float* __restrict__ w2) {
    if (blockIdx.x == 0 && threadIdx.x == 0) g_flag = 0;
    int is64 = detect64(ei);
    for (int i = blockIdx.x * blockDim.x + threadIdx.x; i < N_EDGES;
         i += gridDim.x * blockDim.x) {
        int dst = load_idx(ei, is64, (long long)N_EDGES + i);
        atomicAdd(&g_hist[dst], 1);
    }
    for (int id = blockIdx.x * blockDim.x + threadIdx.x; id < 128 * 512;
         id += gridDim.x * blockDim.x) {
        int kt = id >> 9, r = id & 511;
        int n = r >> 4, kp = r & 15;
        int k0 = kt * 32 + 2 * kp;
        float v0 = w2[(size_t)k0 * 32 + n];
        float v1 = w2[(size_t)(k0 + 1) * 32 + n];
        __nv_bfloat16 h0, l0, h1, l1;
        split_bf(v0, h0, l0);
        split_bf(v1, h1, l1);
        g_w2h[id] = pack_bf(h0, h1);
        g_w2l[id] = pack_bf(l0, l1);
    }
}

// ---------------- launch 2: fused scan (block 0) + scatter (all blocks) -----
__device__ __forceinline__ int block_excl_scan1024(int v, int* ws) {
    int tid = threadIdx.x;
    int lane = tid & 31, wid = tid >> 5;
    int incl = v;
#pragma unroll
    for (int o = 1; o < 32; o <<= 1) {
        int nv = __shfl_up_sync(0xffffffffu, incl, o);
        if (lane >= o) incl += nv;
    }
    if (lane == 31) ws[wid] = incl;
    __syncthreads();
    if (wid == 0) {
        int wv = ws[lane];
#pragma unroll
        for (int o = 1; o < 32; o <<= 1) {
            int nv = __shfl_up_sync(0xffffffffu, wv, o);
            if (lane >= o) wv += nv;
        }
        ws[lane] = wv;
    }
    __syncthreads();
    int base = (wid > 0) ? ws[wid - 1] : 0;
    return base + incl - v;
}

__global__ void __launch_bounds__(1024) k_scan_scatter(const void* __restrict__ ei) {
    __shared__ int ws[32];
    __shared__ int s_carry;
    int tid = threadIdx.x;

    if (blockIdx.x == 0) {
        if (tid == 0) s_carry = 0;
        __syncthreads();
        for (int base = 0; base < N_NODES; base += 1024) {
            int idx = base + tid;
            int v = (idx < N_NODES) ? g_hist[idx] : 0;
            int ex = block_excl_scan1024(v, ws);
            int c = s_carry;
            if (idx < N_NODES) {
                g_off[idx] = c + ex;
                g_cursor[idx] = c + ex;
                g_hist[idx] = 0;
            }
            __syncthreads();
            if (tid == 1023) s_carry = c + ex + v;
            __syncthreads();
        }
        if (tid == 0) {
            g_off[N_NODES] = N_EDGES;
            __threadfence();
            *(volatile int*)&g_flag = 1;
        }
        __syncthreads();
    } else {
        if (tid == 0) {
            while (*(volatile int*)&g_flag == 0) __nanosleep(200);
        }
        __syncthreads();
        __threadfence();
    }

    int is64 = detect64(ei);
    for (int i = blockIdx.x * 1024 + tid; i < N_EDGES; i += gridDim.x * 1024) {
        int dst = load_idx(ei, is64, (long long)N_EDGES + i);
        int pos = atomicAdd(&g_cursor[dst], 1);
        g_perm[pos] = i;
    }
}

// ---------------- launch 3: A build (R11 exact) ------------------------------
__device__ __forceinline__ void stage_edges(int estart, int cnt, int tid,
                                            int is64, const void* ei,
                                            const float* ea, const float* x,
                                            int* s_e, int* s_src,
                                            float4 (*s_ea)[4],
                                            float4 (*s_xj)[8]) {
    __syncthreads();
    for (int j = tid; j < cnt; j += 128) {
        int e = g_perm[estart + j];
        s_e[j] = e;
        s_src[j] = load_idx(ei, is64, e);
    }
    __syncthreads();
    for (int idx = tid; idx < cnt * 4; idx += 128) {
        int j = idx >> 2, q = idx & 3;
        s_ea[j][q] = ((const float4*)(ea + (size_t)s_e[j] * EDGE_DIM))[q];
    }
    for (int idx = tid; idx < cnt * 8; idx += 128) {
        int j = idx >> 3, q = idx & 7;
        s_xj[j][q] = ((const float4*)(x + (size_t)s_src[j] * IN_C))[q];
    }
    __syncthreads();
}

__device__ __forceinline__ void accum_edge(int j, int tid,
                                           const unsigned long long* w1r2,
                                           float b1v,
                                           unsigned long long* acc2, float& xs,
                                           float4 (*s_ea)[4],
                                           float4 (*s_xj)[8]) {
    float4 e0 = s_ea[j][0], e1 = s_ea[j][1], e2 = s_ea[j][2], e3 = s_ea[j][3];
    unsigned long long h2a = mul2(pack2(e0.x, e0.y), w1r2[0]);
    unsigned long long h2b = mul2(pack2(e0.z, e0.w), w1r2[1]);
    fma2(h2a, pack2(e1.x, e1.y), w1r2[2]);
    fma2(h2b, pack2(e1.z, e1.w), w1r2[3]);
    fma2(h2a, pack2(e2.x, e2.y), w1r2[4]);
    fma2(h2b, pack2(e2.z, e2.w), w1r2[5]);
    fma2(h2a, pack2(e3.x, e3.y), w1r2[6]);
    fma2(h2b, pack2(e3.z, e3.w), w1r2[7]);
    float alo, ahi, blo, bhi;
    unpack2(h2a, alo, ahi);
    unpack2(h2b, blo, bhi);
    float he = fmaxf((alo + blo) + (ahi + bhi) + b1v, 0.f);
    unsigned long long he2 = pack2(he, he);
#pragma unroll
    for (int q = 0; q < 8; q++) {
        float4 xv = s_xj[j][q];
        fma2(acc2[2 * q], he2, pack2(xv.x, xv.y));
        fma2(acc2[2 * q + 1], he2, pack2(xv.z, xv.w));
    }
    if (tid < IN_C) xs += ((const float*)s_xj)[j * 32 + tid];
}

__device__ __forceinline__ void store_node(int n, int tid,
                                           const unsigned long long* acc2,
                                           float xs) {
    uint32_t ph[16], pl[16];
#pragma unroll
    for (int m = 0; m < 16; m++) {
        float a0, a1;
        unpack2(acc2[m], a0, a1);
        __nv_bfloat16 h0, l0, h1, l1;
        split_bf(a0, h0, l0);
        split_bf(a1, h1, l1);
        ph[m] = pack_bf(h0, h1);
        pl[m] = pack_bf(l0, l1);
    }
    uint4* aph = (uint4*)(g_Ah + (size_t)n * A_U32 + tid * 16);
    uint4* apl = (uint4*)(g_Al + (size_t)n * A_U32 + tid * 16);
#pragma unroll
    for (int q = 0; q < 4; q++) {
        aph[q] = make_uint4(ph[4 * q], ph[4 * q + 1], ph[4 * q + 2], ph[4 * q + 3]);
        apl[q] = make_uint4(pl[4 * q], pl[4 * q + 1], pl[4 * q + 2], pl[4 * q + 3]);
    }
    if (tid < IN_C) g_xsum[n * IN_C + tid] = xs;
}

__global__ void __launch_bounds__(128, 6) k_abuild(const float* __restrict__ x,
                                                   const void* __restrict__ ei,
                                                   const float* __restrict__ ea,
                                                   const float* __restrict__ w1,
                                                   const float* __restrict__ b1) {
    int tid = threadIdx.x;
    int is64 = detect64(ei);
    int n0 = blockIdx.x * GNODES;
    int nlocal = min(GNODES, N_NODES - n0);

    unsigned long long w1r2[8];
#pragma unroll
    for (int k = 0; k < 8; k++)
        w1r2[k] = pack2(w1[(2 * k) * HIDDEN + tid], w1[(2 * k + 1) * HIDDEN + tid]);
    float b1v = b1[tid];

    __shared__ int s_off[GNODES + 1];
    __shared__ int s_src[ECAP];
    __shared__ int s_e[ECAP];
    __shared__ __align__(16) float4 s_ea[ECAP][4];
    __shared__ __align__(16) float4 s_xj[ECAP][8];

    if (tid <= nlocal) s_off[tid] = g_off[n0 + tid];
    __syncthreads();

    int pnode = 0;
    while (pnode < nlocal) {
        int estart = s_off[pnode];
        int qnode = pnode;
        while (qnode < nlocal && s_off[qnode + 1] - estart <= ECAP) qnode++;

        if (qnode > pnode) {
            int cnt = s_off[qnode] - estart;
            stage_edges(estart, cnt, tid, is64, ei, ea, x, s_e, s_src, s_ea, s_xj);
            for (int nn = pnode; nn < qnode; nn++) {
                unsigned long long acc2[16];
#pragma unroll
                for (int m = 0; m < 16; m++) acc2[m] = 0ull;
                float xs = 0.f;
                int ls = s_off[nn] - estart, le = s_off[nn + 1] - estart;
                for (int j = ls; j < le; j++)
                    accum_edge(j, tid, w1r2, b1v, acc2, xs, s_ea, s_xj);
                store_node(n0 + nn, tid, acc2, xs);
            }
            pnode = qnode;
        } else {
            int d = s_off[pnode + 1] - estart;
            unsigned long long acc2[16];
#pragma unroll
            for (int m = 0; m < 16; m++) acc2[m] = 0ull;
            float xs = 0.f;
            for (int b = 0; b < d; b += ECAP) {
                int cc = min(d - b, ECAP);
                stage_edges(estart + b, cc, tid, is64, ei, ea, x, s_e, s_src,
                            s_ea, s_xj);
                for (int j = 0; j < cc; j++)
                    accum_edge(j, tid, w1r2, b1v, acc2, xs, s_ea, s_xj);
            }
            store_node(n0 + pnode, tid, acc2, xs);
            pnode++;
        }
    }
}

// ---------------- launch 4 (PROFILED): tcgen05 GEMM, cp.async pipeline ------
#if HAS_TC
__device__ __forceinline__ void tc_stage(char* buf, uint32_t bufu, int kt,
                                         int rowbase, int tid) {
    // A_hi / A_lo tiles: 128 rows x 128B, SW128, via cp.async
#pragma unroll
    for (int t = 0; t < 4; t++) {
        int idx = tid + t * 256;           // 0..1023
        int row = idx >> 3, q = idx & 7;
        int mg = rowbase + row;
        bool ok = mg < N_NODES;
        const void* sh = g_Ah + (size_t)mg * A_U32 + kt * 32 + q * 4;
        const void* sl = g_Al + (size_t)mg * A_U32 + kt * 32 + q * 4;
        uint32_t off = swz128((uint32_t)(row * 128 + q * 16));
        cp16(bufu + off, sh, ok);
        cp16(bufu + 16384 + off, sl, ok);
    }
    // W_hi / W_lo tiles: 32 rows x 128B, SW128
    {
        int idx = tid;                     // 0..255
        int n = idx >> 3, g = idx & 7;
        int chunk = kt * 2 + (g >> 2);
        int src = chunk * 512 + n * 16 + (g & 3) * 4;
        uint32_t off = swz128((uint32_t)(n * 128 + g * 16));
        cp16(bufu + 32768 + off, g_w2h + src, true);
        cp16(bufu + 36864 + off, g_w2l + src, true);
    }
    cp_commit();
}
#endif

__global__ void __launch_bounds__(256) k_gemm_main(const float* __restrict__ x,
                                                   const float* __restrict__ b2,
                                                   const float* __restrict__ rw,
                                                   const float* __restrict__ cb) {
#if HAS_TC
    extern __shared__ __align__(16) char DYN[];
    __shared__ __align__(8) unsigned long long s_mb[2];
    __shared__ uint32_t s_tmem[1];

    int tid = threadIdx.x;
    int wid = tid >> 5, lane = tid & 31;
    int rowbase = blockIdx.x * TCM;

    uint32_t dynbase = smem_u32(DYN);
    uint32_t base = (dynbase + 1023u) & ~1023u;
    char* AB = DYN + (base - dynbase);

    uint32_t mb0 = smem_u32(&s_mb[0]);
    uint32_t mb1 = smem_u32(&s_mb[1]);

    if (tid == 0) {
        mbar_init(mb0, 1);
        mbar_init(mb1, 1);
    }
    if (wid == 0) {
        tc_alloc(smem_u32(&s_tmem[0]), 32);
        tc_relinq();
    }
    __syncthreads();
    uint32_t tmem_d = s_tmem[0];

    uint32_t ph0 = 0, ph1 = 0;

    // prologue: issue cp.async for kt=0 into buffer 0
    tc_stage(AB, base, 0, rowbase, tid);

    for (int kt = 0; kt < NK2; kt++) {
        int cur = kt & 1, nxt = cur ^ 1;
        uint32_t bufu = base + cur * BUFSZ;

        // issue cp.async for kt+1 into the other buffer (before waiting on kt)
        if (kt + 1 < NK2) {
            if (kt + 1 >= 2) {
                // buffer nxt last consumed by MMA of kt-1 — wait for that commit
                if (nxt == 0) { mbar_wait(mb0, ph0); ph0 ^= 1; }
                else          { mbar_wait(mb1, ph1); ph1 ^= 1; }
            }
            tc_stage(AB + nxt * BUFSZ, base + nxt * BUFSZ, kt + 1, rowbase, tid);
            cp_wait1();   // kt's group complete; kt+1's may still be in flight
        } else {
            cp_wait0();
        }
        __syncthreads();
        fence_async_shared();

        if (wid == 0 && elect_one()) {
            uint64_t dAh = mk_desc(bufu);
            uint64_t dAl = mk_desc(bufu + 16384);
            uint64_t dWh = mk_desc(bufu + 32768);
            uint64_t dWl = mk_desc(bufu + 36864);
#pragma unroll
            for (int s = 0; s < 4; s++) {
                tc_mma_f16_ss(tmem_d, dAh + 2 * s, dWh + 2 * s, TC_IDESC,
                              !(kt == 0 && s == 0));
                tc_mma_f16_ss(tmem_d, dAh + 2 * s, dWl + 2 * s, TC_IDESC, true);
                tc_mma_f16_ss(tmem_d, dAl + 2 * s, dWh + 2 * s, TC_IDESC, true);
            }
            tc_commit(cur == 0 ? mb0 : mb1);
        }
        __syncthreads();  // all threads see MMA issued before next buffer reuse
    }

    mbar_wait(mb0, ph0);
    mbar_wait(mb1, ph1);
    tc_fence_after();
    __syncthreads();

    float* B2s = (float*)AB;
    float* RWs = (float*)(AB + 4096);
    float* cbs = (float*)(AB + 8192);
    for (int t = tid; t < 1024; t += 256) {
        B2s[t] = b2[t];
        RWs[t] = rw[t];
    }
    if (tid < 32) cbs[tid] = cb[tid];
    __syncthreads();

    // TMEM D read: only warps 0-3 own the 128 TMEM lanes
    if (wid < 4) {
        uint32_t dreg[32];
        tc_ld32(dreg, tmem_d);
        tc_wait_ld();

        int mg = rowbase + wid * 32 + lane;
        if (mg < N_NODES) {
            float cnt = (float)(g_off[mg + 1] - g_off[mg]);
            float inv = 1.f / fmaxf(cnt, 1.f);
            float xr[32], xsr[32];
            const float4* xp = (const float4*)(x + (size_t)mg * IN_C);
            const float4* xsp = (const float4*)(g_xsum + (size_t)mg * IN_C);
#pragma unroll
            for (int q = 0; q < 8; q++) {
                float4 v = xp[q];
                xr[4 * q] = v.x; xr[4 * q + 1] = v.y;
                xr[4 * q + 2] = v.z; xr[4 * q + 3] = v.w;
                float4 s = xsp[q];
                xsr[4 * q] = s.x; xsr[4 * q + 1] = s.y;
                xsr[4 * q + 2] = s.z; xsr[4 * q + 3] = s.w;
            }
#pragma unroll 4
            for (int col = 0; col < 32; col++) {
                float e = 0.f, r = 0.f;
#pragma unroll
                for (int i = 0; i < 32; i++) {
                    e += xsr[i] * B2s[i * 32 + col];
                    r += xr[i] * RWs[i * 32 + col];
                }
                g_h[(size_t)mg * 32 + col] =
                    (__uint_as_float(dreg[col]) + e) * inv + r + cbs[col];
            }
        }
    }

    __syncthreads();
    if (wid == 0) tc_dealloc(tmem_d, 32);
#endif
}

// ---------------- launch 5: R11-exact HMMA GEMM (empty if HAS_TC) -----------
__global__ void __launch_bounds__(256) k_gemm_fb(const float* __restrict__ x,
                                                 const float* __restrict__ b2,
                                                 const float* __restrict__ rw,
                                                 const float* __restrict__ cb) {
#if !HAS_TC
    __shared__ __align__(16) unsigned char SMEM[25600];
    __nv_bfloat16* A_hi = (__nv_bfloat16*)SMEM;
    __nv_bfloat16* A_lo = (__nv_bfloat16*)(SMEM + 10240);
    __nv_bfloat16* Wt_hi = (__nv_bfloat16*)(SMEM + 20480);
    __nv_bfloat16* Wt_lo = (__nv_bfloat16*)(SMEM + 23040);
    float* C_s = (float*)SMEM;
    __shared__ float B2s[1024], RWs[1024], cbs[32];

    int tid = threadIdx.x;
    int warp = tid >> 5, lane = tid & 31;
    int gi = lane >> 2, tq = lane & 3;
    int rowbase = blockIdx.x * FBM;

#pragma unroll
    for (int q = 0; q < 4; q++) {
        int id = tid + q * 256;
        B2s[id] = b2[id];
        RWs[id] = rw[id];
    }
    if (tid < 32) cbs[tid] = cb[tid];

    float c[4][4];
#pragma unroll
    for (int j = 0; j < 4; j++)
#pragma unroll
        for (int r = 0; r < 4; r++) c[j][r] = 0.f;

    int lrow = tid >> 1, half = tid & 1;
    bool rowok = (rowbase + lrow) < N_NODES;
    const uint4* ahsrc =
        (const uint4*)(g_Ah + (size_t)(rowbase + lrow) * A_U32) + half * 2;
    const uint4* alsrc =
        (const uint4*)(g_Al + (size_t)(rowbase + lrow) * A_U32) + half * 2;

    uint4 vah[2], val[2];
    uint32_t wrh[2], wrl[2];

#pragma unroll
    for (int q = 0; q < 2; q++) {
        vah[q] = rowok ? ahsrc[q] : make_uint4(0, 0, 0, 0);
        val[q] = rowok ? alsrc[q] : make_uint4(0, 0, 0, 0);
    }
#pragma unroll
    for (int q = 0; q < 2; q++) {
        int id = tid + q * 256;
        wrh[q] = g_w2h[id];
        wrl[q] = g_w2l[id];
    }
    {
        uint4* dh = (uint4*)((uint32_t*)A_hi + lrow * 20 + half * 8);
        uint4* dl = (uint4*)((uint32_t*)A_lo + lrow * 20 + half * 8);
        dh[0] = vah[0]; dh[1] = vah[1];
        dl[0] = val[0]; dl[1] = val[1];
#pragma unroll
        for (int q = 0; q < 2; q++) {
            int id = tid + q * 256;
            int n = id >> 4, kp = id & 15;
            ((uint32_t*)Wt_hi)[n * 20 + kp] = wrh[q];
            ((uint32_t*)Wt_lo)[n * 20 + kp] = wrl[q];
        }
    }
    __syncthreads();

    for (int kt = 0; kt < FNKT; kt++) {
        int ktn = (kt + 1 < FNKT) ? kt + 1 : kt;
#pragma unroll
        for (int q = 0; q < 2; q++) {
            vah[q] = rowok ? ahsrc[ktn * 4 + q] : make_uint4(0, 0, 0, 0);
            val[q] = rowok ? alsrc[ktn * 4 + q] : make_uint4(0, 0, 0, 0);
        }
#pragma unroll
        for (int q = 0; q < 2; q++) {
            int id = tid + q * 256;
            wrh[q] = g_w2h[ktn * 512 + id];
            wrl[q] = g_w2l[ktn * 512 + id];
        }

        int rb = warp * 16;
#pragma unroll
        for (int kk = 0; kk < FBK; kk += 16) {
            const __nv_bfloat16* ah = &A_hi[(rb + gi) * FASTR + kk + 2 * tq];
            const __nv_bfloat16* al = &A_lo[(rb + gi) * FASTR + kk + 2 * tq];
            uint32_t a0h = lds_u32(ah), a1h = lds_u32(ah + 8 * FASTR);
            uint32_t a2h = lds_u32(ah + 8), a3h = lds_u32(ah + 8 * FASTR + 8);
            uint32_t a0l = lds_u32(al), a1l = lds_u32(al + 8 * FASTR);
            uint32_t a2l = lds_u32(al + 8), a3l = lds_u32(al + 8 * FASTR + 8);
#pragma unroll
            for (int j = 0; j < 4; j++) {
                const __nv_bfloat16* bh = &Wt_hi[(j * 8 + gi) * FWSTR + kk + 2 * tq];
                const __nv_bfloat16* bl = &Wt_lo[(j * 8 + gi) * FWSTR + kk + 2 * tq];
                uint32_t b0h = lds_u32(bh), b1h = lds_u32(bh + 8);
                uint32_t b0l = lds_u32(bl), b1l = lds_u32(bl + 8);
                mma16816(c[j], a0h, a1h, a2h, a3h, b0h, b1h);
                mma16816(c[j], a0h, a1h, a2h, a3h, b0l, b1l);
                mma16816(c[j], a0l, a1l, a2l, a3l, b0h, b1h);
            }
        }
        __syncthreads();

        if (kt + 1 < FNKT) {
            uint4* dh = (uint4*)((uint32_t*)A_hi + lrow * 20 + half * 8);
            uint4* dl = (uint4*)((uint32_t*)A_lo + lrow * 20 + half * 8);
            dh[0] = vah[0]; dh[1] = vah[1];
            dl[0] = val[0]; dl[1] = val[1];
#pragma unroll
            for (int q = 0; q < 2; q++) {
                int id = tid + q * 256;
                int n = id >> 4, kp = id & 15;
                ((uint32_t*)Wt_hi)[n * 20 + kp] = wrh[q];
                ((uint32_t*)Wt_lo)[n * 20 + kp] = wrl[q];
            }
        }
        __syncthreads();
    }

    {
        int rb = warp * 16;
#pragma unroll
        for (int j = 0; j < 4; j++) {
            int col = j * 8 + 2 * tq;
            C_s[(rb + gi) * 32 + col] = c[j][0];
            C_s[(rb + gi) * 32 + col + 1] = c[j][1];
            C_s[(rb + gi + 8) * 32 + col] = c[j][2];
            C_s[(rb + gi + 8) * 32 + col + 1] = c[j][3];
        }
    }
    __syncthreads();

    {
        int row = tid >> 1, ch = tid & 1;
        int mg = rowbase + row;
        if (mg < N_NODES) {
            float cnt = (float)(g_off[mg + 1] - g_off[mg]);
            float inv = 1.f / fmaxf(cnt, 1.f);
            const float4* xsp = (const float4*)(g_xsum + (size_t)mg * IN_C);
            const float4* xp = (const float4*)(x + (size_t)mg * IN_C);
            float eacc[16], racc[16];
#pragma unroll
            for (int cjj = 0; cjj < 16; cjj++) { eacc[cjj] = 0.f; racc[cjj] = 0.f; }
#pragma unroll
            for (int i4 = 0; i4 < 8; i4++) {
                float4 xsv = xsp[i4];
                float4 xvv = xp[i4];
                float sv[4] = {xsv.x, xsv.y, xsv.z, xsv.w};
                float vv[4] = {xvv.x, xvv.y, xvv.z, xvv.w};
#pragma unroll
                for (int ii = 0; ii < 4; ii++) {
                    int i = i4 * 4 + ii;
#pragma unroll
                    for (int cjj = 0; cjj < 16; cjj++) {
                        int col = ch * 16 + cjj;
                        eacc[cjj] += sv[ii] * B2s[i * 32 + col];
                        racc[cjj] += vv[ii] * RWs[i * 32 + col];
                    }
                }
            }
#pragma unroll
            for (int cjj = 0; cjj < 16; cjj++) {
                int col = ch * 16 + cjj;
                g_h[(size_t)mg * 32 + col] =
                    (C_s[row * 32 + col] + eacc[cjj]) * inv + racc[cjj] + cbs[col];
            }
        }
    }
#endif
}

// ---------------- BatchNorm statistics (deterministic, no atomics) ----------
__global__ void k_bnstats() {
    int tid = threadIdx.x;  // 256
    int c = tid & 31, g = tid >> 5;
    double s = 0.0, s2 = 0.0;
    for (int row = blockIdx.x * 8 + g; row < N_NODES; row += gridDim.x * 8) {
        float v = g_h[(size_t)row * 32 + c];
        s += (double)v;
        s2 += (double)v * (double)v;
    }
    __shared__ double sh[256], sh2[256];
    sh[tid] = s; sh2[tid] = s2;
    __syncthreads();
    for (int off = 128; off >= 32; off >>= 1) {
        if (tid < off) { sh[tid] += sh[tid + off]; sh2[tid] += sh2[tid + off]; }
        __syncthreads();
    }
    if (tid < 32) {
        g_psum[blockIdx.x][tid] = sh[tid];
        g_psq[blockIdx.x][tid] = sh2[tid];
    }
}

__global__ void k_bnfin(const float* __restrict__ gamma,
                        const float* __restrict__ beta) {
    int c = threadIdx.x;
    if (c < OUT_C) {
        double s = 0.0, s2 = 0.0;
        for (int b = 0; b < BN_BLOCKS; b++) {
            s += g_psum[b][c];
            s2 += g_psq[b][c];
        }
        double mu = s / (double)N_NODES;
        double var = s2 / (double)N_NODES - mu * mu;
        float rstd = (float)rsqrt(var + (double)BN_EPS);
        float sc = rstd * gamma[c];
        g_scale[c] = sc;
        g_shift[c] = beta[c] - (float)mu * sc;
    }
}

// ---------------- output: x + relu(BN(h)) ------------------------------------
__global__ void k_out(const float* __restrict__ x, float* __restrict__ out) {
    int i = blockIdx.x * blockDim.x + threadIdx.x;
    const int total = N_NODES * OUT_C / 4;
    if (i < total) {
        float4 xv = ((const float4*)x)[i];
        float4 hv = ((const float4*)g_h)[i];
        int c = (i & 7) * 4;
        float4 o;
        o.x = xv.x + fmaxf(hv.x * g_scale[c + 0] + g_shift[c + 0], 0.f);
        o.y = xv.y + fmaxf(hv.y * g_scale[c + 1] + g_shift[c + 1], 0.f);
        o.z = xv.z + fmaxf(hv.z * g_scale[c + 2] + g_shift[c + 2], 0.f);
        o.w = xv.w + fmaxf(hv.w * g_scale[c + 3] + g_shift[c + 3], 0.f);
        ((float4*)out)[i] = o;
    }
}

// ---------------- launch -----------------------------------------------------
extern "C" void kernel_launch(void* const* d_in, const int* in_sizes, int n_in,
                              void* d_out, int out_size) {
    const float* x   = (const float*)d_in[0];
    const void*  ei  = d_in[1];               // int32 or int64, self-detected
    const float* ea  = (const float*)d_in[2];
    const float* w1  = (const float*)d_in[3];
    const float* b1  = (const float*)d_in[4];
    const float* w2  = (const float*)d_in[5];
    const float* b2  = (const float*)d_in[6];
    const float* rw  = (const float*)d_in[7];
    const float* cb  = (const float*)d_in[8];
    const float* gam = (const float*)d_in[9];
    const float* bet = (const float*)d_in[10];
    float* out = (float*)d_out;

    cudaFuncSetAttribute(k_gemm_main, cudaFuncAttributeMaxDynamicSharedMemorySize,
                         TC_DYN);

    k_hist<<<512, 256>>>(ei, w2);                    // launch 1
    k_scan_scatter<<<148, 1024>>>(ei);               // launch 2 (fused)
    k_abuild<<<NGROUPS, 128>>>(x, ei, ea, w1, b1);   // launch 3
    k_gemm_main<<<TCGRID, 256, TC_DYN>>>(x, b2, rw, cb);  // launch 4 (profiled)
    k_gemm_fb<<<TCGRID, 256>>>(x, b2, rw, cb);       // launch 5 (null if TC ran)
    k_bnstats<<<BN_BLOCKS, 256>>>();
    k_bnfin<<<1, 32>>>(gam, bet);
    k_out<<<(N_NODES * OUT_C / 4 + 255) / 256, 256>>>(x, out);
}

// round 17
// speedup vs baseline: 1.2154x; 1.0357x over previous
#include <cuda_runtime.h>
#include <cuda_bf16.h>
#include <cstdint>

#define N_NODES 50000
#define N_EDGES 400000
#define IN_C 32
#define OUT_C 32
#define EDGE_DIM 16
#define HIDDEN 128
#define BN_EPS 1e-5f

#define A_COLS (HIDDEN * IN_C)   // 4096
#define A_U32 (A_COLS / 2)       // 2048 packed u32 per node per plane
#define BN_BLOCKS 232

// tcgen05 GEMM tiling
#define TCM 128
#define KT2 64
#define NK2 (A_COLS / KT2)        // 64
#define TCGRID ((N_NODES + TCM - 1) / TCM)   // 391
#define N_PAD (TCGRID * TCM)      // 50048 rows (tile-complete)
#define BUFSZ 40960
#define TC_DYN (2 * BUFSZ + 1024)
#define TC_IDESC 0x8080490u       // c=F32, a/b=BF16 K-major, M=128, N=32

// fallback tiling
#define FBM 128
#define FBK 32
#define FNKT (A_COLS / FBK)       // 128
#define FASTR 40
#define FWSTR 40

// abuild: node-group blocking
#define GNODES 16
#define ECAP 128
#define NGROUPS ((N_NODES + GNODES - 1) / GNODES)   // 3125

// tcgen05 availability: only in arch-specific ('a') device passes
#if defined(__CUDA_ARCH__) && (defined(__CUDA_ARCH_FEAT_SM103_ALL) || \
    defined(__CUDA_ARCH_FEAT_SM100_ALL) || defined(__CUDA_ARCH_FEAT_SM101_ALL) || \
    defined(__CUDA_ARCH_SPECIFIC__))
#define HAS_TC 1
#else
#define HAS_TC 0
#endif

// ---------------- static device scratch (no allocations allowed) ------------
// A planes in TILE-MAJOR layout: [nblk][kt][row 0..127][32 u32]
// tile(nblk, kt) = contiguous 16 KB; u32 index =
//   ((nblk*64 + kt) * 128 + row) * 32 + c,   c = (h&1)*16 + ipair, kt = h>>1
__device__ uint32_t g_Ah[(size_t)N_PAD * A_U32];
__device__ uint32_t g_Al[(size_t)N_PAD * A_U32];
__device__ uint32_t g_w2h[128 * 512];
__device__ uint32_t g_w2l[128 * 512];
__device__ float g_xsum[(size_t)N_NODES * IN_C];
__device__ float g_h[(size_t)N_NODES * OUT_C];
__device__ int   g_hist[N_NODES];   // zero at load; re-zeroed by scan each run
__device__ int   g_off[N_NODES + 1];
__device__ int   g_cursor[N_NODES];
__device__ int   g_perm[N_EDGES];
__device__ int   g_flag;            // scan->scatter release; reset by k_hist
__device__ double g_psum[BN_BLOCKS][OUT_C];
__device__ double g_psq[BN_BLOCKS][OUT_C];
__device__ float g_scale[OUT_C];
__device__ float g_shift[OUT_C];

// ---------------- helpers ----------------------------------------------------
__device__ __forceinline__ void split_bf(float v, __nv_bfloat16& h,
                                         __nv_bfloat16& l) {
    h = __float2bfloat16_rn(v);
    l = __float2bfloat16_rn(v - __bfloat162float(h));
}

__device__ __forceinline__ uint32_t pack_bf(__nv_bfloat16 a, __nv_bfloat16 b) {
    __nv_bfloat162 p;
    p.x = a; p.y = b;
    return *reinterpret_cast<uint32_t*>(&p);
}

__device__ __forceinline__ uint32_t lds_u32(const __nv_bfloat16* p) {
    return *reinterpret_cast<const uint32_t*>(p);
}

__device__ __forceinline__ void mma16816(float c[4], uint32_t a0, uint32_t a1,
                                         uint32_t a2, uint32_t a3, uint32_t b0,
                                         uint32_t b1) {
    asm volatile(
        "mma.sync.aligned.m16n8k16.row.col.f32.bf16.bf16.f32 "
        "{%0,%1,%2,%3}, {%4,%5,%6,%7}, {%8,%9}, {%0,%1,%2,%3};"
        : "+f"(c[0]), "+f"(c[1]), "+f"(c[2]), "+f"(c[3])
        : "r"(a0), "r"(a1), "r"(a2), "r"(a3), "r"(b0), "r"(b1));
}

// packed f32x2 ops (sm_100+)
__device__ __forceinline__ unsigned long long pack2(float a, float b) {
    unsigned long long r;
    asm("mov.b64 %0, {%1, %2};" : "=l"(r) : "f"(a), "f"(b));
    return r;
}
__device__ __forceinline__ void unpack2(unsigned long long v, float& a, float& b) {
    asm("mov.b64 {%0, %1}, %2;" : "=f"(a), "=f"(b) : "l"(v));
}
__device__ __forceinline__ void fma2(unsigned long long& d, unsigned long long a,
                                     unsigned long long b) {
    asm("fma.rn.f32x2 %0, %1, %2, %0;" : "+l"(d) : "l"(a), "l"(b));
}
__device__ __forceinline__ unsigned long long mul2(unsigned long long a,
                                                   unsigned long long b) {
    unsigned long long r;
    asm("mul.rn.f32x2 %0, %1, %2;" : "=l"(r) : "l"(a), "l"(b));
    return r;
}

// self-detecting edge-index load (int32 vs int64 buffer layout)
__device__ __forceinline__ int detect64(const void* ei) {
    const int* p = (const int*)ei;
    return (p[1] == 0) & (p[3] == 0) & (p[5] == 0) & (p[7] == 0);
}
__device__ __forceinline__ int load_idx(const void* ei, int is64, long long elem) {
    int v = is64 ? (int)((const long long*)ei)[elem] : ((const int*)ei)[elem];
    return min(max(v, 0), N_NODES - 1);
}

// ---------------- smem primitives --------------------------------------------
__device__ __forceinline__ uint32_t smem_u32(const void* p) {
    uint32_t a;
    asm("{ .reg .u64 t; cvta.to.shared.u64 t, %1; cvt.u32.u64 %0, t; }"
        : "=r"(a) : "l"(p));
    return a;
}
__device__ __forceinline__ uint32_t swz128(uint32_t off) {
    return off ^ ((off >> 3) & 0x70);
}

// cp.async 16B copy with zero-fill when invalid
__device__ __forceinline__ void cp16(uint32_t dst, const void* src, bool valid) {
    int sz = valid ? 16 : 0;
    asm volatile("cp.async.cg.shared.global [%0], [%1], 16, %2;"
                 :: "r"(dst), "l"(src), "r"(sz) : "memory");
}
__device__ __forceinline__ void cp_commit() {
    asm volatile("cp.async.commit_group;" ::: "memory");
}
__device__ __forceinline__ void cp_wait0() {
    asm volatile("cp.async.wait_group 0;" ::: "memory");
}
__device__ __forceinline__ void cp_wait1() {
    asm volatile("cp.async.wait_group 1;" ::: "memory");
}

#if HAS_TC
__device__ __forceinline__ uint32_t elect_one() {
    uint32_t pred;
    asm volatile("{\n\t.reg .pred p;\n\telect.sync _|p, 0xFFFFFFFF;\n\t"
                 "selp.b32 %0, 1, 0, p;\n\t}" : "=r"(pred));
    return pred;
}
__device__ __forceinline__ void mbar_init(uint32_t a, uint32_t c) {
    asm volatile("mbarrier.init.shared.b64 [%0], %1;" :: "r"(a), "r"(c) : "memory");
}
__device__ __forceinline__ void mbar_wait(uint32_t a, uint32_t par) {
    asm volatile(
        "{\n\t.reg .pred P;\n\t"
        "WL%=:\n\t"
        "mbarrier.try_wait.parity.acquire.cta.shared::cta.b64 P, [%0], %1;\n\t"
        "@!P bra WL%=;\n\t}"
        :: "r"(a), "r"(par) : "memory");
}
__device__ __forceinline__ void tc_alloc(uint32_t slot, uint32_t ncols) {
    asm volatile("tcgen05.alloc.cta_group::1.sync.aligned.shared::cta.b32 [%0], %1;"
                 :: "r"(slot), "r"(ncols) : "memory");
}
__device__ __forceinline__ void tc_relinq() {
    asm volatile("tcgen05.relinquish_alloc_permit.cta_group::1.sync.aligned;");
}
__device__ __forceinline__ void tc_dealloc(uint32_t base, uint32_t ncols) {
    asm volatile("tcgen05.dealloc.cta_group::1.sync.aligned.b32 %0, %1;"
                 :: "r"(base), "r"(ncols));
}
__device__ __forceinline__ void tc_commit(uint32_t mbar) {
    asm volatile(
        "tcgen05.commit.cta_group::1.mbarrier::arrive::one.shared::cluster.b64 [%0];"
        :: "r"(mbar) : "memory");
}
__device__ __forceinline__ void tc_fence_after() {
    asm volatile("tcgen05.fence::after_thread_sync;" ::: "memory");
}
__device__ __forceinline__ void fence_async_shared() {
    asm volatile("fence.proxy.async.shared::cta;" ::: "memory");
}
__device__ __forceinline__ void tc_mma_f16_ss(uint32_t d, uint64_t a, uint64_t b,
                                              uint32_t idesc, bool acc) {
    uint32_t en = acc ? 1u : 0u;
    asm volatile(
        "{\n\t.reg .pred p;\n\tsetp.ne.u32 p, %5, 0;\n\t"
        "tcgen05.mma.cta_group::1.kind::f16 [%0], %1, %2, %3, {%4, %4, %4, %4}, p;\n\t}"
        :: "r"(d), "l"(a), "l"(b), "r"(idesc), "r"(0u), "r"(en) : "memory");
}
__device__ __forceinline__ void tc_ld32(uint32_t* r, uint32_t addr) {
    asm volatile(
        "tcgen05.ld.sync.aligned.32x32b.x32.b32 "
        "{%0,%1,%2,%3,%4,%5,%6,%7,%8,%9,%10,%11,%12,%13,%14,%15,"
        "%16,%17,%18,%19,%20,%21,%22,%23,%24,%25,%26,%27,%28,%29,%30,%31}, [%32];"
        : "=r"(r[0]), "=r"(r[1]), "=r"(r[2]), "=r"(r[3]), "=r"(r[4]), "=r"(r[5]),
          "=r"(r[6]), "=r"(r[7]), "=r"(r[8]), "=r"(r[9]), "=r"(r[10]), "=r"(r[11]),
          "=r"(r[12]), "=r"(r[13]), "=r"(r[14]), "=r"(r[15]), "=r"(r[16]),
          "=r"(r[17]), "=r"(r[18]), "=r"(r[19]), "=r"(r[20]), "=r"(r[21]),
          "=r"(r[22]), "=r"(r[23]), "=r"(r[24]), "=r"(r[25]), "=r"(r[26]),
          "=r"(r[27]), "=r"(r[28]), "=r"(r[29]), "=r"(r[30]), "=r"(r[31])
        : "r"(addr));
}
__device__ __forceinline__ void tc_wait_ld() {
    asm volatile("tcgen05.wait::ld.sync.aligned;" ::: "memory");
}
__device__ __forceinline__ uint64_t mk_desc(uint32_t base) {
    return ((uint64_t)2 << 61) | ((uint64_t)1 << 46) | ((uint64_t)64 << 32) |
           ((uint64_t)1 << 16) | ((uint64_t)(base >> 4) & 0x3FFF);
}
#endif  // HAS_TC

// ---------------- launch 1: histogram + W2 pre-split + flag reset ------------
__global__ void k_hist(const void* __restrict__ ei, const float* __restrict__ w2) {
    if (blockIdx.x == 0 && threadIdx.x == 0) g_flag = 0;
    int is64 = detect64(ei);
    for (int i = blockIdx.x * blockDim.x + threadIdx.x; i < N_EDGES;
         i += gridDim.x * blockDim.x) {
        int dst = load_idx(ei, is64, (long long)N_EDGES + i);
        atomicAdd(&g_hist[dst], 1);
    }
    for (int id = blockIdx.x * blockDim.x + threadIdx.x; id < 128 * 512;
         id += gridDim.x * blockDim.x) {
        int kt = id >> 9, r = id & 511;
        int n = r >> 4, kp = r & 15;
        int k0 = kt * 32 + 2 * kp;
        float v0 = w2[(size_t)k0 * 32 + n];
        float v1 = w2[(size_t)(k0 + 1) * 32 + n];
        __nv_bfloat16 h0, l0, h1, l1;
        split_bf(v0, h0, l0);
        split_bf(v1, h1, l1);
        g_w2h[id] = pack_bf(h0, h1);
        g_w2l[id] = pack_bf(l0, l1);
    }
}

// ---------------- launch 2: fused scan (block 0) + scatter (all blocks) -----
__device__ __forceinline__ int block_excl_scan1024(int v, int* ws) {
    int tid = threadIdx.x;
    int lane = tid & 31, wid = tid >> 5;
    int incl = v;
#pragma unroll
    for (int o = 1; o < 32; o <<= 1) {
        int nv = __shfl_up_sync(0xffffffffu, incl, o);
        if (lane >= o) incl += nv;
    }
    if (lane == 31) ws[wid] = incl;
    __syncthreads();
    if (wid == 0) {
        int wv = ws[lane];
#pragma unroll
        for (int o = 1; o < 32; o <<= 1) {
            int nv = __shfl_up_sync(0xffffffffu, wv, o);
            if (lane >= o) wv += nv;
        }
        ws[lane] = wv;
    }
    __syncthreads();
    int base = (wid > 0) ? ws[wid - 1] : 0;
    return base + incl - v;
}

__global__ void __launch_bounds__(1024) k_scan_scatter(const void* __restrict__ ei) {
    __shared__ int ws[32];
    __shared__ int s_carry;
    int tid = threadIdx.x;

    if (blockIdx.x == 0) {
        if (tid == 0) s_carry = 0;
        __syncthreads();
        for (int base = 0; base < N_NODES; base += 1024) {
            int idx = base + tid;
            int v = (idx < N_NODES) ? g_hist[idx] : 0;
            int ex = block_excl_scan1024(v, ws);
            int c = s_carry;
            if (idx < N_NODES) {
                g_off[idx] = c + ex;
                g_cursor[idx] = c + ex;
                g_hist[idx] = 0;
            }
            __syncthreads();
            if (tid == 1023) s_carry = c + ex + v;
            __syncthreads();
        }
        if (tid == 0) {
            g_off[N_NODES] = N_EDGES;
            __threadfence();
            *(volatile int*)&g_flag = 1;
        }
        __syncthreads();
    } else {
        if (tid == 0) {
            while (*(volatile int*)&g_flag == 0) __nanosleep(200);
        }
        __syncthreads();
        __threadfence();
    }

    int is64 = detect64(ei);
    for (int i = blockIdx.x * 1024 + tid; i < N_EDGES; i += gridDim.x * 1024) {
        int dst = load_idx(ei, is64, (long long)N_EDGES + i);
        int pos = atomicAdd(&g_cursor[dst], 1);
        g_perm[pos] = i;
    }
}

// ---------------- launch 3: A build (R11 math, tile-major A stores) ---------
__device__ __forceinline__ void stage_edges(int estart, int cnt, int tid,
                                            int is64, const void* ei,
                                            const float* ea, const float* x,
                                            int* s_e, int* s_src,
                                            float4 (*s_ea)[4],
                                            float4 (*s_xj)[8]) {
    __syncthreads();
    for (int j = tid; j < cnt; j += 128) {
        int e = g_perm[estart + j];
        s_e[j] = e;
        s_src[j] = load_idx(ei, is64, e);
    }
    __syncthreads();
    for (int idx = tid; idx < cnt * 4; idx += 128) {
        int j = idx >> 2, q = idx & 3;
        s_ea[j][q] = ((const float4*)(ea + (size_t)s_e[j] * EDGE_DIM))[q];
    }
    for (int idx = tid; idx < cnt * 8; idx += 128) {
        int j = idx >> 3, q = idx & 7;
        s_xj[j][q] = ((const float4*)(x + (size_t)s_src[j] * IN_C))[q];
    }
    __syncthreads();
}

__device__ __forceinline__ void accum_edge(int j, int tid,
                                           const unsigned long long* w1r2,
                                           float b1v,
                                           unsigned long long* acc2, float& xs,
                                           float4 (*s_ea)[4],
                                           float4 (*s_xj)[8]) {
    float4 e0 = s_ea[j][0], e1 = s_ea[j][1], e2 = s_ea[j][2], e3 = s_ea[j][3];
    unsigned long long h2a = mul2(pack2(e0.x, e0.y), w1r2[0]);
    unsigned long long h2b = mul2(pack2(e0.z, e0.w), w1r2[1]);
    fma2(h2a, pack2(e1.x, e1.y), w1r2[2]);
    fma2(h2b, pack2(e1.z, e1.w), w1r2[3]);
    fma2(h2a, pack2(e2.x, e2.y), w1r2[4]);
    fma2(h2b, pack2(e2.z, e2.w), w1r2[5]);
    fma2(h2a, pack2(e3.x, e3.y), w1r2[6]);
    fma2(h2b, pack2(e3.z, e3.w), w1r2[7]);
    float alo, ahi, blo, bhi;
    unpack2(h2a, alo, ahi);
    unpack2(h2b, blo, bhi);
    float he = fmaxf((alo + blo) + (ahi + bhi) + b1v, 0.f);
    unsigned long long he2 = pack2(he, he);
#pragma unroll
    for (int q = 0; q < 8; q++) {
        float4 xv = s_xj[j][q];
        fma2(acc2[2 * q], he2, pack2(xv.x, xv.y));
        fma2(acc2[2 * q + 1], he2, pack2(xv.z, xv.w));
    }
    if (tid < IN_C) xs += ((const float*)s_xj)[j * 32 + tid];
}

__device__ __forceinline__ void store_node(int n, int tid,
                                           const unsigned long long* acc2,
                                           float xs) {
    uint32_t ph[16], pl[16];
#pragma unroll
    for (int m = 0; m < 16; m++) {
        float a0, a1;
        unpack2(acc2[m], a0, a1);
        __nv_bfloat16 h0, l0, h1, l1;
        split_bf(a0, h0, l0);
        split_bf(a1, h1, l1);
        ph[m] = pack_bf(h0, h1);
        pl[m] = pack_bf(l0, l1);
    }
    // tile-major: tile (n>>7, tid>>1), row n&127, col (tid&1)*16
    size_t tb = (((size_t)(n >> 7) * 64 + (tid >> 1)) * 128 + (n & 127)) * 32 +
                (tid & 1) * 16;
    uint4* aph = (uint4*)(g_Ah + tb);
    uint4* apl = (uint4*)(g_Al + tb);
#pragma unroll
    for (int q = 0; q < 4; q++) {
        aph[q] = make_uint4(ph[4 * q], ph[4 * q + 1], ph[4 * q + 2], ph[4 * q + 3]);
        apl[q] = make_uint4(pl[4 * q], pl[4 * q + 1], pl[4 * q + 2], pl[4 * q + 3]);
    }
    if (tid < IN_C) g_xsum[n * IN_C + tid] = xs;
}

__global__ void __launch_bounds__(128, 6) k_abuild(const float* __restrict__ x,
                                                   const void* __restrict__ ei,
                                                   const float* __restrict__ ea,
                                                   const float* __restrict__ w1,
                                                   const float* __restrict__ b1) {
    int tid = threadIdx.x;
    int is64 = detect64(ei);
    int n0 = blockIdx.x * GNODES;
    int nlocal = min(GNODES, N_NODES - n0);

    unsigned long long w1r2[8];
#pragma unroll
    for (int k = 0; k < 8; k++)
        w1r2[k] = pack2(w1[(2 * k) * HIDDEN + tid], w1[(2 * k + 1) * HIDDEN + tid]);
    float b1v = b1[tid];

    __shared__ int s_off[GNODES + 1];
    __shared__ int s_src[ECAP];
    __shared__ int s_e[ECAP];
    __shared__ __align__(16) float4 s_ea[ECAP][4];
    __shared__ __align__(16) float4 s_xj[ECAP][8];

    if (tid <= nlocal) s_off[tid] = g_off[n0 + tid];
    __syncthreads();

    int pnode = 0;
    while (pnode < nlocal) {
        int estart = s_off[pnode];
        int qnode = pnode;
        while (qnode < nlocal && s_off[qnode + 1] - estart <= ECAP) qnode++;

        if (qnode > pnode) {
            int cnt = s_off[qnode] - estart;
            stage_edges(estart, cnt, tid, is64, ei, ea, x, s_e, s_src, s_ea, s_xj);
            for (int nn = pnode; nn < qnode; nn++) {
                unsigned long long acc2[16];
#pragma unroll
                for (int m = 0; m < 16; m++) acc2[m] = 0ull;
                float xs = 0.f;
                int ls = s_off[nn] - estart, le = s_off[nn + 1] - estart;
                for (int j = ls; j < le; j++)
                    accum_edge(j, tid, w1r2, b1v, acc2, xs, s_ea, s_xj);
                store_node(n0 + nn, tid, acc2, xs);
            }
            pnode = qnode;
        } else {
            int d = s_off[pnode + 1] - estart;
            unsigned long long acc2[16];
#pragma unroll
            for (int m = 0; m < 16; m++) acc2[m] = 0ull;
            float xs = 0.f;
            for (int b = 0; b < d; b += ECAP) {
                int cc = min(d - b, ECAP);
                stage_edges(estart + b, cc, tid, is64, ei, ea, x, s_e, s_src,
                            s_ea, s_xj);
                for (int j = 0; j < cc; j++)
                    accum_edge(j, tid, w1r2, b1v, acc2, xs, s_ea, s_xj);
            }
            store_node(n0 + pnode, tid, acc2, xs);
            pnode++;
        }
    }
}

// ---------------- launch 4 (PROFILED): tcgen05 GEMM, contiguous tile loads --
#if HAS_TC
__device__ __forceinline__ void tc_stage(uint32_t bufu, int kt, int nblk,
                                         int rowbase, int tid) {
    // A tiles now contiguous 16 KB each in tile-major layout
    const uint32_t* tAh = g_Ah + ((size_t)nblk * 64 + kt) * 4096;
    const uint32_t* tAl = g_Al + ((size_t)nblk * 64 + kt) * 4096;
#pragma unroll
    for (int t = 0; t < 4; t++) {
        int idx = tid + t * 256;           // 0..1023
        int row = idx >> 3, q = idx & 7;
        bool ok = (rowbase + row) < N_NODES;
        uint32_t off = swz128((uint32_t)(row * 128 + q * 16));
        cp16(bufu + off, tAh + row * 32 + q * 4, ok);
        cp16(bufu + 16384 + off, tAl + row * 32 + q * 4, ok);
    }
    // W_hi / W_lo tiles: 32 rows x 128B, SW128
    {
        int idx = tid;                     // 0..255
        int n = idx >> 3, g = idx & 7;
        int chunk = kt * 2 + (g >> 2);
        int src = chunk * 512 + n * 16 + (g & 3) * 4;
        uint32_t off = swz128((uint32_t)(n * 128 + g * 16));
        cp16(bufu + 32768 + off, g_w2h + src, true);
        cp16(bufu + 36864 + off, g_w2l + src, true);
    }
    cp_commit();
}
#endif

__global__ void __launch_bounds__(256) k_gemm_main(const float* __restrict__ x,
                                                   const float* __restrict__ b2,
                                                   const float* __restrict__ rw,
                                                   const float* __restrict__ cb) {
#if HAS_TC
    extern __shared__ __align__(16) char DYN[];
    __shared__ __align__(8) unsigned long long s_mb[2];
    __shared__ uint32_t s_tmem[1];

    int tid = threadIdx.x;
    int wid = tid >> 5, lane = tid & 31;
    int nblk = blockIdx.x;
    int rowbase = nblk * TCM;

    uint32_t dynbase = smem_u32(DYN);
    uint32_t base = (dynbase + 1023u) & ~1023u;
    char* AB = DYN + (base - dynbase);

    uint32_t mb0 = smem_u32(&s_mb[0]);
    uint32_t mb1 = smem_u32(&s_mb[1]);

    if (tid == 0) {
        mbar_init(mb0, 1);
        mbar_init(mb1, 1);
    }
    if (wid == 0) {
        tc_alloc(smem_u32(&s_tmem[0]), 32);
        tc_relinq();
    }
    __syncthreads();
    uint32_t tmem_d = s_tmem[0];

    uint32_t ph0 = 0, ph1 = 0;

    // prologue: issue cp.async for kt=0 into buffer 0
    tc_stage(base, 0, nblk, rowbase, tid);

    for (int kt = 0; kt < NK2; kt++) {
        int cur = kt & 1, nxt = cur ^ 1;
        uint32_t bufu = base + cur * BUFSZ;

        if (kt + 1 < NK2) {
            if (kt + 1 >= 2) {
                if (nxt == 0) { mbar_wait(mb0, ph0); ph0 ^= 1; }
                else          { mbar_wait(mb1, ph1); ph1 ^= 1; }
            }
            tc_stage(base + nxt * BUFSZ, kt + 1, nblk, rowbase, tid);
            cp_wait1();
        } else {
            cp_wait0();
        }
        __syncthreads();
        fence_async_shared();

        if (wid == 0 && elect_one()) {
            uint64_t dAh = mk_desc(bufu);
            uint64_t dAl = mk_desc(bufu + 16384);
            uint64_t dWh = mk_desc(bufu + 32768);
            uint64_t dWl = mk_desc(bufu + 36864);
#pragma unroll
            for (int s = 0; s < 4; s++) {
                tc_mma_f16_ss(tmem_d, dAh + 2 * s, dWh + 2 * s, TC_IDESC,
                              !(kt == 0 && s == 0));
                tc_mma_f16_ss(tmem_d, dAh + 2 * s, dWl + 2 * s, TC_IDESC, true);
                tc_mma_f16_ss(tmem_d, dAl + 2 * s, dWh + 2 * s, TC_IDESC, true);
            }
            tc_commit(cur == 0 ? mb0 : mb1);
        }
        __syncthreads();
    }

    mbar_wait(mb0, ph0);
    mbar_wait(mb1, ph1);
    tc_fence_after();
    __syncthreads();

    float* B2s = (float*)AB;
    float* RWs = (float*)(AB + 4096);
    float* cbs = (float*)(AB + 8192);
    for (int t = tid; t < 1024; t += 256) {
        B2s[t] = b2[t];
        RWs[t] = rw[t];
    }
    if (tid < 32) cbs[tid] = cb[tid];
    __syncthreads();

    if (wid < 4) {
        uint32_t dreg[32];
        tc_ld32(dreg, tmem_d);
        tc_wait_ld();

        int mg = rowbase + wid * 32 + lane;
        if (mg < N_NODES) {
            float cnt = (float)(g_off[mg + 1] - g_off[mg]);
            float inv = 1.f / fmaxf(cnt, 1.f);
            float xr[32], xsr[32];
            const float4* xp = (const float4*)(x + (size_t)mg * IN_C);
            const float4* xsp = (const float4*)(g_xsum + (size_t)mg * IN_C);
#pragma unroll
            for (int q = 0; q < 8; q++) {
                float4 v = xp[q];
                xr[4 * q] = v.x; xr[4 * q + 1] = v.y;
                xr[4 * q + 2] = v.z; xr[4 * q + 3] = v.w;
                float4 s = xsp[q];
                xsr[4 * q] = s.x; xsr[4 * q + 1] = s.y;
                xsr[4 * q + 2] = s.z; xsr[4 * q + 3] = s.w;
            }
#pragma unroll 4
            for (int col = 0; col < 32; col++) {
                float e = 0.f, r = 0.f;
#pragma unroll
                for (int i = 0; i < 32; i++) {
                    e += xsr[i] * B2s[i * 32 + col];
                    r += xr[i] * RWs[i * 32 + col];
                }
                g_h[(size_t)mg * 32 + col] =
                    (__uint_as_float(dreg[col]) + e) * inv + r + cbs[col];
            }
        }
    }

    __syncthreads();
    if (wid == 0) tc_dealloc(tmem_d, 32);
#endif
}

// ---------------- launch 5: HMMA GEMM fallback (empty if HAS_TC) ------------
__global__ void __launch_bounds__(256) k_gemm_fb(const float* __restrict__ x,
                                                 const float* __restrict__ b2,
                                                 const float* __restrict__ rw,
                                                 const float* __restrict__ cb) {
#if !HAS_TC
    __shared__ __align__(16) unsigned char SMEM[25600];
    __nv_bfloat16* A_hi = (__nv_bfloat16*)SMEM;
    __nv_bfloat16* A_lo = (__nv_bfloat16*)(SMEM + 10240);
    __nv_bfloat16* Wt_hi = (__nv_bfloat16*)(SMEM + 20480);
    __nv_bfloat16* Wt_lo = (__nv_bfloat16*)(SMEM + 23040);
    float* C_s = (float*)SMEM;
    __shared__ float B2s[1024], RWs[1024], cbs[32];

    int tid = threadIdx.x;
    int warp = tid >> 5, lane = tid & 31;
    int gi = lane >> 2, tq = lane & 3;
    int nblk = blockIdx.x;
    int rowbase = nblk * FBM;

#pragma unroll
    for (int q = 0; q < 4; q++) {
        int id = tid + q * 256;
        B2s[id] = b2[id];
        RWs[id] = rw[id];
    }
    if (tid < 32) cbs[tid] = cb[tid];

    float c[4][4];
#pragma unroll
    for (int j = 0; j < 4; j++)
#pragma unroll
        for (int r = 0; r < 4; r++) c[j][r] = 0.f;

    int lrow = tid >> 1, half = tid & 1;
    bool rowok = (rowbase + lrow) < N_NODES;

    for (int kt = 0; kt < FNKT; kt++) {
        // tile-major A: fbk tile kt covers tcgen05 tile kt/2, halves by kt&1
        int kt2 = kt >> 1, sub = kt & 1;
        size_t tb = (((size_t)nblk * 64 + kt2) * 128 + lrow) * 32 + sub * 16 +
                    half * 8;
#pragma unroll
        for (int q = 0; q < 2; q++) {
            uint4 vh = rowok ? ((const uint4*)(g_Ah + tb))[q]
                             : make_uint4(0, 0, 0, 0);
            uint4 vl = rowok ? ((const uint4*)(g_Al + tb))[q]
                             : make_uint4(0, 0, 0, 0);
            ((uint4*)((uint32_t*)A_hi + lrow * 20 + half * 8))[q] = vh;
            ((uint4*)((uint32_t*)A_lo + lrow * 20 + half * 8))[q] = vl;
        }
#pragma unroll
        for (int q = 0; q < 2; q++) {
            int id = tid + q * 256;
            int n = id >> 4, kp = id & 15;
            ((uint32_t*)Wt_hi)[n * 20 + kp] = g_w2h[kt * 512 + id];
            ((uint32_t*)Wt_lo)[n * 20 + kp] = g_w2l[kt * 512 + id];
        }
        __syncthreads();

        int rb = warp * 16;
#pragma unroll
        for (int kk = 0; kk < FBK; kk += 16) {
            const __nv_bfloat16* ah = &A_hi[(rb + gi) * FASTR + kk + 2 * tq];
            const __nv_bfloat16* al = &A_lo[(rb + gi) * FASTR + kk + 2 * tq];
            uint32_t a0h = lds_u32(ah), a1h = lds_u32(ah + 8 * FASTR);
            uint32_t a2h = lds_u32(ah + 8), a3h = lds_u32(ah + 8 * FASTR + 8);
            uint32_t a0l = lds_u32(al), a1l = lds_u32(al + 8 * FASTR);
            uint32_t a2l = lds_u32(al + 8), a3l = lds_u32(al + 8 * FASTR + 8);
#pragma unroll
            for (int j = 0; j < 4; j++) {
                const __nv_bfloat16* bh = &Wt_hi[(j * 8 + gi) * FWSTR + kk + 2 * tq];
                const __nv_bfloat16* bl = &Wt_lo[(j * 8 + gi) * FWSTR + kk + 2 * tq];
                uint32_t b0h = lds_u32(bh), b1h = lds_u32(bh + 8);
                uint32_t b0l = lds_u32(bl), b1l = lds_u32(bl + 8);
                mma16816(c[j], a0h, a1h, a2h, a3h, b0h, b1h);
                mma16816(c[j], a0h, a1h, a2h, a3h, b0l, b1l);
                mma16816(c[j], a0l, a1l, a2l, a3l, b0h, b1h);
            }
        }
        __syncthreads();
    }

    {
        int rb = warp * 16;
#pragma unroll
        for (int j = 0; j < 4; j++) {
            int col = j * 8 + 2 * tq;
            C_s[(rb + gi) * 32 + col] = c[j][0];
            C_s[(rb + gi) * 32 + col + 1] = c[j][1];
            C_s[(rb + gi + 8) * 32 + col] = c[j][2];
            C_s[(rb + gi + 8) * 32 + col + 1] = c[j][3];
        }
    }
    __syncthreads();

    {
        int row = tid >> 1, ch = tid & 1;
        int mg = rowbase + row;
        if (mg < N_NODES) {
            float cnt = (float)(g_off[mg + 1] - g_off[mg]);
            float inv = 1.f / fmaxf(cnt, 1.f);
            const float4* xsp = (const float4*)(g_xsum + (size_t)mg * IN_C);
            const float4* xp = (const float4*)(x + (size_t)mg * IN_C);
            float eacc[16], racc[16];
#pragma unroll
            for (int cjj = 0; cjj < 16; cjj++) { eacc[cjj] = 0.f; racc[cjj] = 0.f; }
#pragma unroll
            for (int i4 = 0; i4 < 8; i4++) {
                float4 xsv = xsp[i4];
                float4 xvv = xp[i4];
                float sv[4] = {xsv.x, xsv.y, xsv.z, xsv.w};
                float vv[4] = {xvv.x, xvv.y, xvv.z, xvv.w};
#pragma unroll
                for (int ii = 0; ii < 4; ii++) {
                    int i = i4 * 4 + ii;
#pragma unroll
                    for (int cjj = 0; cjj < 16; cjj++) {
                        int col = ch * 16 + cjj;
                        eacc[cjj] += sv[ii] * B2s[i * 32 + col];
                        racc[cjj] += vv[ii] * RWs[i * 32 + col];
                    }
                }
            }
#pragma unroll
            for (int cjj = 0; cjj < 16; cjj++) {
                int col = ch * 16 + cjj;
                g_h[(size_t)mg * 32 + col] =
                    (C_s[row * 32 + col] + eacc[cjj]) * inv + racc[cjj] + cbs[col];
            }
        }
    }
#endif
}

// ---------------- BatchNorm statistics (deterministic, no atomics) ----------
__global__ void k_bnstats() {
    int tid = threadIdx.x;  // 256
    int c = tid & 31, g = tid >> 5;
    double s = 0.0, s2 = 0.0;
    for (int row = blockIdx.x * 8 + g; row < N_NODES; row += gridDim.x * 8) {
        float v = g_h[(size_t)row * 32 + c];
        s += (double)v;
        s2 += (double)v * (double)v;
    }
    __shared__ double sh[256], sh2[256];
    sh[tid] = s; sh2[tid] = s2;
    __syncthreads();
    for (int off = 128; off >= 32; off >>= 1) {
        if (tid < off) { sh[tid] += sh[tid + off]; sh2[tid] += sh2[tid + off]; }
        __syncthreads();
    }
    if (tid < 32) {
        g_psum[blockIdx.x][tid] = sh[tid];
        g_psq[blockIdx.x][tid] = sh2[tid];
    }
}

__global__ void k_bnfin(const float* __restrict__ gamma,
                        const float* __restrict__ beta) {
    int c = threadIdx.x;
    if (c < OUT_C) {
        double s = 0.0, s2 = 0.0;
        for (int b = 0; b < BN_BLOCKS; b++) {
            s += g_psum[b][c];
            s2 += g_psq[b][c];
        }
        double mu = s / (double)N_NODES;
        double var = s2 / (double)N_NODES - mu * mu;
        float rstd = (float)rsqrt(var + (double)BN_EPS);
        float sc = rstd * gamma[c];
        g_scale[c] = sc;
        g_shift[c] = beta[c] - (float)mu * sc;
    }
}

// ---------------- output: x + relu(BN(h)) ------------------------------------
__global__ void k_out(const float* __restrict__ x, float* __restrict__ out) {
    int i = blockIdx.x * blockDim.x + threadIdx.x;
    const int total = N_NODES * OUT_C / 4;
    if (i < total) {
        float4 xv = ((const float4*)x)[i];
        float4 hv = ((const float4*)g_h)[i];
        int c = (i & 7) * 4;
        float4 o;
        o.x = xv.x + fmaxf(hv.x * g_scale[c + 0] + g_shift[c + 0], 0.f);
        o.y = xv.y + fmaxf(hv.y * g_scale[c + 1] + g_shift[c + 1], 0.f);
        o.z = xv.z + fmaxf(hv.z * g_scale[c + 2] + g_shift[c + 2], 0.f);
        o.w = xv.w + fmaxf(hv.w * g_scale[c + 3] + g_shift[c + 3], 0.f);
        ((float4*)out)[i] = o;
    }
}

// ---------------- launch -----------------------------------------------------
extern "C" void kernel_launch(void* const* d_in, const int* in_sizes, int n_in,
                              void* d_out, int out_size) {
    const float* x   = (const float*)d_in[0];
    const void*  ei  = d_in[1];               // int32 or int64, self-detected
    const float* ea  = (const float*)d_in[2];
    const float* w1  = (const float*)d_in[3];
    const float* b1  = (const float*)d_in[4];
    const float* w2  = (const float*)d_in[5];
    const float* b2  = (const float*)d_in[6];
    const float* rw  = (const float*)d_in[7];
    const float* cb  = (const float*)d_in[8];
    const float* gam = (const float*)d_in[9];
    const float* bet = (const float*)d_in[10];
    float* out = (float*)d_out;

    cudaFuncSetAttribute(k_gemm_main, cudaFuncAttributeMaxDynamicSharedMemorySize,
                         TC_DYN);

    k_hist<<<512, 256>>>(ei, w2);                    // launch 1
    k_scan_scatter<<<148, 1024>>>(ei);               // launch 2 (fused)
    k_abuild<<<NGROUPS, 128>>>(x, ei, ea, w1, b1);   // launch 3
    k_gemm_main<<<TCGRID, 256, TC_DYN>>>(x, b2, rw, cb);  // launch 4 (profiled)
    k_gemm_fb<<<TCGRID, 256>>>(x, b2, rw, cb);       // launch 5 (null if TC ran)
    k_bnstats<<<BN_BLOCKS, 256>>>();
    k_bnfin<<<1, 32>>>(gam, bet);
    k_out<<<(N_NODES * OUT_C / 4 + 255) / 256, 256>>>(x, out);
}